// round 13
// baseline (speedup 1.0000x reference)
#include <cuda_runtime.h>
#include <cuda_fp16.h>
#include <math.h>

#define SEQ 2048
#define DIM 2880
#define NH 64
#define NKV 8
#define HD 64
#define QDIM (NH*HD)     // 4096
#define KVDIM (NKV*HD)   // 512
#define QKVN 5120        // 4096 + 512 + 512
#define KOFF 4096
#define VOFF 4608
#define WINDOW 128

typedef __half f16;

// fp32 scratch
__device__ float g_qkv[SEQ * QKVN];    // 40 MB: q | k | v per row
__device__ float g_bqkv[QKVN];

// fp16 operand scratch
__device__ f16 g_x16[SEQ * DIM];       // x (fp16)
__device__ f16 g_wc[QKVN * DIM];       // concat wq|wk|wv (fp16)
__device__ f16 g_wo[DIM * QDIM];       // wo (fp16)
__device__ f16 g_a16[SEQ * QDIM];      // attn out (fp16)

// ---------------------------------------------------------------------------
// Fused prep: x -> fp16, wq/wk/wv -> wc fp16, wo -> fp16, bias concat.
// ---------------------------------------------------------------------------
#define R0 (SEQ*DIM/8)
#define R1 (QDIM*DIM/8)
#define R2 (KVDIM*DIM/8)
#define R3 (KVDIM*DIM/8)
#define R4 ((size_t)DIM*QDIM/8)
#define R5 (QKVN/8)
#define PREP_THREADS (R0+R1+R2+R3+R4+R5)

__device__ __forceinline__ void conv8(const float* __restrict__ s, f16* __restrict__ d) {
    float4 a = *(const float4*)s;
    float4 b = *(const float4*)(s + 4);
    __half2 hh[4];
    hh[0] = __halves2half2(__float2half_rn(a.x), __float2half_rn(a.y));
    hh[1] = __halves2half2(__float2half_rn(a.z), __float2half_rn(a.w));
    hh[2] = __halves2half2(__float2half_rn(b.x), __float2half_rn(b.y));
    hh[3] = __halves2half2(__float2half_rn(b.z), __float2half_rn(b.w));
    *(uint4*)d = *(uint4*)hh;
}

__global__ void prep(const float* __restrict__ x,
                     const float* __restrict__ wq, const float* __restrict__ wk,
                     const float* __restrict__ wv, const float* __restrict__ wo,
                     const float* __restrict__ qb, const float* __restrict__ kb,
                     const float* __restrict__ vb,
                     f16* __restrict__ x16,
                     f16* __restrict__ wc, f16* __restrict__ wo16,
                     float* __restrict__ bqkv)
{
    long t = (long)blockIdx.x * blockDim.x + threadIdx.x;
    if (t < (long)R0) { conv8(x + t * 8, x16 + t * 8); return; }
    t -= R0;
    if (t < (long)R1) { conv8(wq + t * 8, wc + t * 8); return; }
    t -= R1;
    if (t < (long)R2) { conv8(wk + t * 8, wc + (size_t)KOFF * DIM + t * 8); return; }
    t -= R2;
    if (t < (long)R3) { conv8(wv + t * 8, wc + (size_t)VOFF * DIM + t * 8); return; }
    t -= R3;
    if (t < (long)R4) { conv8(wo + t * 8, wo16 + t * 8); return; }
    t -= R4;
    if (t < (long)R5) {
        const int i = (int)t * 8;
#pragma unroll
        for (int j = 0; j < 8; j++) {
            const int c = i + j;
            bqkv[c] = (c < KOFF) ? qb[c] : (c < VOFF ? kb[c - KOFF] : vb[c - VOFF]);
        }
    }
}

// ---------------------------------------------------------------------------
// fp16 mma.sync GEMM (NT): C = A*B^T + bias
// Block 256x128, BK=64, 3-stage cp.async ring, SW128-swizzled 128B rows,
// 256 thr = 8 warps (4m x 2n), warp tile 64x64 (smem-traffic optimal).
// 1 CTA/SM, 144 KB smem. Requires M%256==0, K%64==0; N guarded.
// ---------------------------------------------------------------------------
#define TILEA 32768u                // A tile: 256 rows x 128 bytes
#define TILEBB 16384u               // B tile: 128 rows x 128 bytes
#define STAGEB (TILEA + TILEBB)     // 48 KB
#define NSTG 3
#define GSMEM_BYTES (NSTG*STAGEB)   // 144 KB

__device__ __forceinline__ void cpa16(unsigned dst, const void* src) {
    asm volatile("cp.async.cg.shared.global [%0], [%1], 16;" :: "r"(dst), "l"(src));
}
__device__ __forceinline__ void cpa16p(unsigned dst, const void* src, int sz) {
    asm volatile("cp.async.cg.shared.global [%0], [%1], 16, %2;"
                 :: "r"(dst), "l"(src), "r"(sz));
}

__global__ __launch_bounds__(256, 1) void gemm_f16(
    const f16* __restrict__ A, const f16* __restrict__ B,
    const float* __restrict__ bias, float* __restrict__ C,
    int M, int N, int K)
{
    extern __shared__ char dsm[];
    unsigned sb;
    { unsigned long long t = __cvta_generic_to_shared(dsm); sb = (unsigned)t; }

    const int tid  = threadIdx.x;
    const int wid  = tid >> 5;
    const int lane = tid & 31;
    const int bm   = blockIdx.y * 256;
    const int bn   = blockIdx.x * 128;
    const int wm   = (wid & 3) * 64;     // 0,64,128,192
    const int wn   = (wid >> 2) * 64;    // 0,64
    const int g    = lane >> 2;
    const int tg   = lane & 3;

    const int KT = K / 64;

    const int r0c = tid >> 3;            // base row 0..31 (stride 32)
    const int c0c = tid & 7;             // 16B segment 0..7

#define SWOFF(r, c) ((unsigned)((r) * 128 + ((((c) ^ ((r) & 7))) << 4)))

#define ISSUE_STAGE(sidx, k0)                                                  \
    do {                                                                       \
        const unsigned tb = sb + (unsigned)(sidx) * STAGEB;                    \
        _Pragma("unroll")                                                      \
        for (int it = 0; it < 8; it++) {                                       \
            const int r = r0c + it * 32;                                       \
            const size_t ao = (size_t)(bm + r) * K + (k0) + c0c * 8;           \
            cpa16(tb + SWOFF(r, c0c), A + ao);                                 \
        }                                                                      \
        _Pragma("unroll")                                                      \
        for (int it = 0; it < 4; it++) {                                       \
            const int r = r0c + it * 32;                                       \
            const int brw = bn + r;                                            \
            const int pz  = (brw < N) ? 16 : 0;                                \
            const size_t bo = (size_t)((brw < N) ? brw : 0) * K + (k0) + c0c * 8; \
            cpa16p(tb + TILEA + SWOFF(r, c0c), B + bo, pz);                    \
        }                                                                      \
        asm volatile("cp.async.commit_group;");                                \
    } while (0)

    float acc[4][8][4];
#pragma unroll
    for (int mi = 0; mi < 4; mi++)
#pragma unroll
        for (int ni = 0; ni < 8; ni++)
#pragma unroll
            for (int r = 0; r < 4; r++) acc[mi][ni][r] = 0.f;

    ISSUE_STAGE(0, 0);
    ISSUE_STAGE(1, 64);

    const int a_row = ((lane >> 3) & 1) * 8 + (lane & 7);
    const int a_ch  = (lane >> 4) & 1;
    const int b_row = ((lane >> 4) & 1) * 8 + (lane & 7);
    const int b_ch  = (lane >> 3) & 1;

    for (int kt = 0; kt < KT; kt++) {
        asm volatile("cp.async.wait_group %0;" :: "n"(1));
        __syncthreads();

        if (kt + 2 < KT) ISSUE_STAGE((kt + 2) % NSTG, (kt + 2) * 64);
        else             asm volatile("cp.async.commit_group;");

        const unsigned stb = sb + (unsigned)(kt % NSTG) * STAGEB;

#pragma unroll
        for (int ks = 0; ks < 4; ks++) {
            unsigned fA[4][4], fB[8][2];
            const int ca = ks * 2 + a_ch;
            const int cb = ks * 2 + b_ch;

#pragma unroll
            for (int mi = 0; mi < 4; mi++) {
                const int r = wm + mi * 16 + a_row;
                const unsigned ad = stb + SWOFF(r, ca);
                asm volatile("ldmatrix.sync.aligned.m8n8.x4.shared.b16 {%0,%1,%2,%3}, [%4];"
                    : "=r"(fA[mi][0]), "=r"(fA[mi][1]), "=r"(fA[mi][2]), "=r"(fA[mi][3])
                    : "r"(ad));
            }
#pragma unroll
            for (int p = 0; p < 4; p++) {
                const int r = wn + p * 16 + b_row;
                const unsigned bd = stb + TILEA + SWOFF(r, cb);
                asm volatile("ldmatrix.sync.aligned.m8n8.x4.shared.b16 {%0,%1,%2,%3}, [%4];"
                    : "=r"(fB[2*p][0]), "=r"(fB[2*p][1]), "=r"(fB[2*p+1][0]), "=r"(fB[2*p+1][1])
                    : "r"(bd));
            }

#define MMA(d, a, b)                                                           \
    asm volatile("mma.sync.aligned.m16n8k16.row.col.f32.f16.f16.f32 "          \
                 "{%0,%1,%2,%3}, {%4,%5,%6,%7}, {%8,%9}, {%0,%1,%2,%3};"       \
                 : "+f"((d)[0]), "+f"((d)[1]), "+f"((d)[2]), "+f"((d)[3])      \
                 : "r"((a)[0]), "r"((a)[1]), "r"((a)[2]), "r"((a)[3]),         \
                   "r"((b)[0]), "r"((b)[1]))

#pragma unroll
            for (int ni = 0; ni < 8; ni++)
#pragma unroll
                for (int mi = 0; mi < 4; mi++)
                    MMA(acc[mi][ni], fA[mi], fB[ni]);
#undef MMA
        }
    }

    // epilogue
#pragma unroll
    for (int mi = 0; mi < 4; mi++) {
        const int row = bm + wm + mi * 16 + g;
#pragma unroll
        for (int ni = 0; ni < 8; ni++) {
            const int col = bn + wn + ni * 8 + tg * 2;
            if (col < N) {
                const float bx = bias[col], by = bias[col + 1];
                float2 v0 = make_float2(acc[mi][ni][0] + bx, acc[mi][ni][1] + by);
                float2 v1 = make_float2(acc[mi][ni][2] + bx, acc[mi][ni][3] + by);
                *(float2*)(C + (size_t)row * N + col)       = v0;
                *(float2*)(C + (size_t)(row + 8) * N + col) = v1;
            }
        }
    }
#undef ISSUE_STAGE
#undef SWOFF
}

// ---------------------------------------------------------------------------
// Fused RoPE: q heads (cols 0..4095) + k heads (cols 4096..4607), in-place.
// ---------------------------------------------------------------------------
__global__ void rope_all(float* __restrict__ t, const float* __restrict__ rope)
{
    const int idx = blockIdx.x * blockDim.x + threadIdx.x;
    const int total = SEQ * (NH + NKV) * 32;
    if (idx >= total) return;
    const int d  = idx & 31;
    const int hh = (idx >> 5) % (NH + NKV);
    const int s  = idx / (32 * (NH + NKV));
    const int coff = (hh < NH) ? hh * HD : KOFF + (hh - NH) * HD;

    const float c1 = rope[s * 128 + d];
    const float c2 = rope[s * 128 + d + 32];
    const float s1 = rope[s * 128 + 64 + d];
    const float s2 = rope[s * 128 + 96 + d];

    float* base = t + (size_t)s * QKVN + coff;
    const float x1 = base[d];
    const float x2 = base[d + 32];
    base[d]      = x1 * c1 - x2 * s1;
    base[d + 32] = x2 * c2 + x1 * s2;
}

// ---------------------------------------------------------------------------
// smem-staged sliding-window attention + sink gating, query-inner blocked.
// CTA = (head, 32 queries). Warp = 4 queries processed together.
// ---------------------------------------------------------------------------
#define JMAX 160
#define ASMEM_FLOATS (2*JMAX*64 + 8*4*64 + 8*JMAX*4)  // sK, sV, shq, shp
#define ASMEM_BYTES  (ASMEM_FLOATS*4)                 // 110592

__global__ __launch_bounds__(256, 2) void attn_kernel(
    const float* __restrict__ qkv, const float* __restrict__ sinks,
    f16* __restrict__ o16)
{
    extern __shared__ float asm_[];
    float* sK  = asm_;                    // [160][64], rotated 16B chunks
    float* sV  = asm_ + JMAX * 64;        // [160][64], plain
    float* shq = asm_ + 2 * JMAX * 64;    // [8][4][64]
    float* shp = shq + 8 * 4 * 64;        // [8][160][4]

    const float scale = 0.16832169945461f;  // (0.1*ln(32)+1)/8
    const int tid  = threadIdx.x;
    const int w    = tid >> 5;
    const int lane = tid & 31;
    const int h    = blockIdx.x >> 6;
    const int ib   = blockIdx.x & 63;
    const int i0   = ib * 32;
    const int kvh  = h >> 3;

    int jmin = i0 - (WINDOW - 1); if (jmin < 0) jmin = 0;
    const int jcnt = i0 + 31 - jmin + 1;   // <= 159

    for (int idx = tid; idx < jcnt * 16; idx += 256) {
        const int row = idx >> 4, c4 = idx & 15;
        const size_t rb = (size_t)(jmin + row) * QKVN + kvh * HD;
        *(float4*)(sK + row * 64 + (((c4 + row) & 15) << 2)) =
            *(const float4*)(qkv + rb + KOFF + c4 * 4);
        *(float4*)(sV + row * 64 + (c4 << 2)) =
            *(const float4*)(qkv + rb + VOFF + c4 * 4);
    }

    const int iw = i0 + w * 4;
    float* q_ = shq + w * 256;
#pragma unroll
    for (int qi = 0; qi < 4; qi++) {
        const float* qrow = qkv + (size_t)(iw + qi) * QKVN + h * HD;
        q_[qi * 64 + lane]      = qrow[lane];
        q_[qi * 64 + lane + 32] = qrow[lane + 32];
    }
    __syncthreads();

    int wlo = iw - (WINDOW - 1); if (wlo < 0) wlo = 0;
    const int cntw = iw + 3 - wlo + 1;     // <= 131
    const int roff = wlo - jmin;           // >= 0

    int rr[5]; bool inb[5];
#pragma unroll
    for (int t = 0; t < 5; t++) {
        const int jj = lane + 32 * t;
        inb[t] = (jj < cntw);
        int r = roff + jj;
        if (r > JMAX - 1) r = JMAX - 1;
        rr[t] = r;
    }

    float dot[5][4];
#pragma unroll
    for (int t = 0; t < 5; t++)
#pragma unroll
        for (int qi = 0; qi < 4; qi++) dot[t][qi] = 0.f;

#pragma unroll
    for (int d4 = 0; d4 < 16; d4++) {
        float4 qv[4];
#pragma unroll
        for (int qi = 0; qi < 4; qi++)
            qv[qi] = *(const float4*)(q_ + qi * 64 + d4 * 4);
#pragma unroll
        for (int t = 0; t < 5; t++) {
            const int r = rr[t];
            const float4 kk = *(const float4*)(sK + r * 64 + (((d4 + r) & 15) << 2));
#pragma unroll
            for (int qi = 0; qi < 4; qi++) {
                dot[t][qi] = fmaf(kk.x, qv[qi].x, dot[t][qi]);
                dot[t][qi] = fmaf(kk.y, qv[qi].y, dot[t][qi]);
                dot[t][qi] = fmaf(kk.z, qv[qi].z, dot[t][qi]);
                dot[t][qi] = fmaf(kk.w, qv[qi].w, dot[t][qi]);
            }
        }
    }

    const float snk = sinks[h];
#pragma unroll
    for (int qi = 0; qi < 4; qi++) {
        const int i = iw + qi;
        float s[5];
#pragma unroll
        for (int t = 0; t < 5; t++) {
            const int j = wlo + lane + 32 * t;
            const bool v = inb[t] && (j <= i) && (j >= i - (WINDOW - 1));
            s[t] = v ? dot[t][qi] * scale : -1e30f;
        }
        float m = fmaxf(fmaxf(fmaxf(s[0], s[1]), fmaxf(s[2], s[3])), s[4]);
#pragma unroll
        for (int o = 16; o; o >>= 1) m = fmaxf(m, __shfl_xor_sync(0xffffffffu, m, o));
        float sum = 0.f;
#pragma unroll
        for (int t = 0; t < 5; t++) { s[t] = expf(s[t] - m); sum += s[t]; }
#pragma unroll
        for (int o = 16; o; o >>= 1) sum += __shfl_xor_sync(0xffffffffu, sum, o);
        const float lse = m + logf(sum);
        const float wsc = (1.f / (1.f + expf(snk - lse))) / sum;
#pragma unroll
        for (int t = 0; t < 5; t++) dot[t][qi] = s[t] * wsc;
    }

    float* p_ = shp + w * (JMAX * 4);
#pragma unroll
    for (int t = 0; t < 5; t++) {
        const int jj = lane + 32 * t;
        *(float4*)(p_ + jj * 4) =
            make_float4(dot[t][0], dot[t][1], dot[t][2], dot[t][3]);
    }
    __syncwarp();

    float a[4][2];
#pragma unroll
    for (int qi = 0; qi < 4; qi++) { a[qi][0] = 0.f; a[qi][1] = 0.f; }

    const float* vb0 = sV + roff * 64;
    for (int jrel = 0; jrel < cntw; jrel++) {
        const float4 p4 = *(const float4*)(p_ + jrel * 4);
        const float v0 = vb0[jrel * 64 + lane];
        const float v1 = vb0[jrel * 64 + lane + 32];
        a[0][0] = fmaf(p4.x, v0, a[0][0]); a[0][1] = fmaf(p4.x, v1, a[0][1]);
        a[1][0] = fmaf(p4.y, v0, a[1][0]); a[1][1] = fmaf(p4.y, v1, a[1][1]);
        a[2][0] = fmaf(p4.z, v0, a[2][0]); a[2][1] = fmaf(p4.z, v1, a[2][1]);
        a[3][0] = fmaf(p4.w, v0, a[3][0]); a[3][1] = fmaf(p4.w, v1, a[3][1]);
    }

#pragma unroll
    for (int qi = 0; qi < 4; qi++) {
        const size_t ob = (size_t)(iw + qi) * QDIM + h * HD;
        o16[ob + lane]      = __float2half_rn(a[qi][0]);
        o16[ob + lane + 32] = __float2half_rn(a[qi][1]);
    }
}

// ---------------------------------------------------------------------------
extern "C" void kernel_launch(void* const* d_in, const int* in_sizes, int n_in,
                              void* d_out, int out_size)
{
    const float* x     = (const float*)d_in[0];
    const float* rope  = (const float*)d_in[1];
    const float* wq_w  = (const float*)d_in[2];
    const float* wq_b  = (const float*)d_in[3];
    const float* wk_w  = (const float*)d_in[4];
    const float* wk_b  = (const float*)d_in[5];
    const float* wv_w  = (const float*)d_in[6];
    const float* wv_b  = (const float*)d_in[7];
    const float* wo_w  = (const float*)d_in[8];
    const float* wo_b  = (const float*)d_in[9];
    const float* sinks = (const float*)d_in[10];
    float* out = (float*)d_out;

    float *qkv, *bqkv;
    cudaGetSymbolAddress((void**)&qkv,  g_qkv);
    cudaGetSymbolAddress((void**)&bqkv, g_bqkv);

    f16 *x16, *wc, *wo, *a16;
    cudaGetSymbolAddress((void**)&x16, g_x16);
    cudaGetSymbolAddress((void**)&wc, g_wc); cudaGetSymbolAddress((void**)&wo, g_wo);
    cudaGetSymbolAddress((void**)&a16, g_a16);

    cudaFuncSetAttribute(gemm_f16, cudaFuncAttributeMaxDynamicSharedMemorySize,
                         GSMEM_BYTES);
    cudaFuncSetAttribute(attn_kernel, cudaFuncAttributeMaxDynamicSharedMemorySize,
                         ASMEM_BYTES);

    // fused prep
    prep<<<(unsigned)((PREP_THREADS + 255) / 256), 256>>>(
        x, wq_w, wk_w, wv_w, wo_w, wq_b, wk_b, wv_b,
        x16, wc, wo, bqkv);

    // fused QKV projection: [2048 x 5120], 320 CTAs (256x128 tiles)
    gemm_f16<<<dim3(QKVN / 128, SEQ / 256), 256, GSMEM_BYTES>>>(
        x16, wc, bqkv, qkv, SEQ, QKVN, DIM);

    // fused RoPE (q + k)
    rope_all<<<(SEQ * (NH + NKV) * 32 + 255) / 256, 256>>>(qkv, rope);

    // query-inner blocked attention
    attn_kernel<<<NH * (SEQ / 32), 256, ASMEM_BYTES>>>(qkv, sinks, a16);

    // O-projection
    gemm_f16<<<dim3((DIM + 127) / 128, SEQ / 256), 256, GSMEM_BYTES>>>(
        a16, wo, wo_b, out, SEQ, DIM, QDIM);
}

// round 14
// speedup vs baseline: 1.1596x; 1.1596x over previous
#include <cuda_runtime.h>
#include <cuda_fp16.h>
#include <math.h>

#define SEQ 2048
#define DIM 2880
#define NH 64
#define NKV 8
#define HD 64
#define QDIM (NH*HD)     // 4096
#define KVDIM (NKV*HD)   // 512
#define QKVN 5120        // 4096 + 512 + 512
#define KOFF 4096
#define VOFF 4608
#define WINDOW 128

typedef __half f16;

// fp32 scratch
__device__ float g_qkv[SEQ * QKVN];    // 40 MB: q | k | v per row
__device__ float g_bqkv[QKVN];

// fp16 operand scratch
__device__ f16 g_x16[SEQ * DIM];       // x (fp16)
__device__ f16 g_wc[QKVN * DIM];       // concat wq|wk|wv (fp16)
__device__ f16 g_wo[DIM * QDIM];       // wo (fp16)
__device__ f16 g_a16[SEQ * QDIM];      // attn out (fp16)

// ---------------------------------------------------------------------------
// Fused prep: x -> fp16, wq/wk/wv -> wc fp16, wo -> fp16, bias concat.
// ---------------------------------------------------------------------------
#define R0 (SEQ*DIM/8)
#define R1 (QDIM*DIM/8)
#define R2 (KVDIM*DIM/8)
#define R3 (KVDIM*DIM/8)
#define R4 ((size_t)DIM*QDIM/8)
#define R5 (QKVN/8)
#define PREP_THREADS (R0+R1+R2+R3+R4+R5)

__device__ __forceinline__ void conv8(const float* __restrict__ s, f16* __restrict__ d) {
    float4 a = *(const float4*)s;
    float4 b = *(const float4*)(s + 4);
    __half2 hh[4];
    hh[0] = __halves2half2(__float2half_rn(a.x), __float2half_rn(a.y));
    hh[1] = __halves2half2(__float2half_rn(a.z), __float2half_rn(a.w));
    hh[2] = __halves2half2(__float2half_rn(b.x), __float2half_rn(b.y));
    hh[3] = __halves2half2(__float2half_rn(b.z), __float2half_rn(b.w));
    *(uint4*)d = *(uint4*)hh;
}

__global__ void prep(const float* __restrict__ x,
                     const float* __restrict__ wq, const float* __restrict__ wk,
                     const float* __restrict__ wv, const float* __restrict__ wo,
                     const float* __restrict__ qb, const float* __restrict__ kb,
                     const float* __restrict__ vb,
                     f16* __restrict__ x16,
                     f16* __restrict__ wc, f16* __restrict__ wo16,
                     float* __restrict__ bqkv)
{
    long t = (long)blockIdx.x * blockDim.x + threadIdx.x;
    if (t < (long)R0) { conv8(x + t * 8, x16 + t * 8); return; }
    t -= R0;
    if (t < (long)R1) { conv8(wq + t * 8, wc + t * 8); return; }
    t -= R1;
    if (t < (long)R2) { conv8(wk + t * 8, wc + (size_t)KOFF * DIM + t * 8); return; }
    t -= R2;
    if (t < (long)R3) { conv8(wv + t * 8, wc + (size_t)VOFF * DIM + t * 8); return; }
    t -= R3;
    if (t < (long)R4) { conv8(wo + t * 8, wo16 + t * 8); return; }
    t -= R4;
    if (t < (long)R5) {
        const int i = (int)t * 8;
#pragma unroll
        for (int j = 0; j < 8; j++) {
            const int c = i + j;
            bqkv[c] = (c < KOFF) ? qb[c] : (c < VOFF ? kb[c - KOFF] : vb[c - VOFF]);
        }
    }
}

// ---------------------------------------------------------------------------
// fp16 mma.sync GEMM (NT): C = A*B^T + bias   [R11-proven config]
// Block 128x128, BK=64, 3-stage cp.async ring, SW128-swizzled 128B rows,
// 256 thr = 8 warps (4m x 2n), warp tile 32x64. 2 CTAs/SM (192KB smem).
// ---------------------------------------------------------------------------
#define TILEB 16384u                // one operand tile: 128 rows x 128 bytes
#define STAGEB (2u*TILEB)           // A, B = 32 KB
#define NSTG 3
#define GSMEM_BYTES (NSTG*STAGEB)   // 96 KB

__device__ __forceinline__ void cpa16(unsigned dst, const void* src) {
    asm volatile("cp.async.cg.shared.global [%0], [%1], 16;" :: "r"(dst), "l"(src));
}
__device__ __forceinline__ void cpa16p(unsigned dst, const void* src, int sz) {
    asm volatile("cp.async.cg.shared.global [%0], [%1], 16, %2;"
                 :: "r"(dst), "l"(src), "r"(sz));
}

__global__ __launch_bounds__(256, 2) void gemm_f16(
    const f16* __restrict__ A, const f16* __restrict__ B,
    const float* __restrict__ bias, float* __restrict__ C,
    int M, int N, int K)
{
    extern __shared__ char dsm[];
    unsigned sb;
    { unsigned long long t = __cvta_generic_to_shared(dsm); sb = (unsigned)t; }

    const int tid  = threadIdx.x;
    const int wid  = tid >> 5;
    const int lane = tid & 31;
    const int bm   = blockIdx.y * 128;
    const int bn   = blockIdx.x * 128;
    const int wm   = (wid & 3) * 32;
    const int wn   = (wid >> 2) * 64;
    const int g    = lane >> 2;
    const int tg   = lane & 3;

    const int KT = K / 64;

    const int r0c = tid >> 3;            // base row 0..31 (stride 32)
    const int c0c = tid & 7;             // 16B segment 0..7

#define SWOFF(r, c) ((unsigned)((r) * 128 + ((((c) ^ ((r) & 7))) << 4)))

#define ISSUE_STAGE(sidx, k0)                                                  \
    do {                                                                       \
        const unsigned tb = sb + (unsigned)(sidx) * STAGEB;                    \
        _Pragma("unroll")                                                      \
        for (int it = 0; it < 4; it++) {                                       \
            const int r = r0c + it * 32;                                       \
            const unsigned so = SWOFF(r, c0c);                                 \
            const size_t ao = (size_t)(bm + r) * K + (k0) + c0c * 8;           \
            const int brw = bn + r;                                            \
            const int pz  = (brw < N) ? 16 : 0;                                \
            const size_t bo = (size_t)((brw < N) ? brw : 0) * K + (k0) + c0c * 8; \
            cpa16 (tb + so,         A + ao);                                   \
            cpa16p(tb + TILEB + so, B + bo, pz);                               \
        }                                                                      \
        asm volatile("cp.async.commit_group;");                                \
    } while (0)

    float acc[2][8][4];
#pragma unroll
    for (int mi = 0; mi < 2; mi++)
#pragma unroll
        for (int ni = 0; ni < 8; ni++)
#pragma unroll
            for (int r = 0; r < 4; r++) acc[mi][ni][r] = 0.f;

    ISSUE_STAGE(0, 0);
    ISSUE_STAGE(1, 64);

    const int a_row = ((lane >> 3) & 1) * 8 + (lane & 7);
    const int a_ch  = (lane >> 4) & 1;
    const int b_row = ((lane >> 4) & 1) * 8 + (lane & 7);
    const int b_ch  = (lane >> 3) & 1;

    for (int kt = 0; kt < KT; kt++) {
        asm volatile("cp.async.wait_group %0;" :: "n"(1));
        __syncthreads();

        if (kt + 2 < KT) ISSUE_STAGE((kt + 2) % NSTG, (kt + 2) * 64);
        else             asm volatile("cp.async.commit_group;");

        const unsigned stb = sb + (unsigned)(kt % NSTG) * STAGEB;

#pragma unroll
        for (int ks = 0; ks < 4; ks++) {
            unsigned fA[2][4], fB[8][2];
            const int ca = ks * 2 + a_ch;
            const int cb = ks * 2 + b_ch;

#pragma unroll
            for (int mi = 0; mi < 2; mi++) {
                const int r = wm + mi * 16 + a_row;
                const unsigned ad = stb + SWOFF(r, ca);
                asm volatile("ldmatrix.sync.aligned.m8n8.x4.shared.b16 {%0,%1,%2,%3}, [%4];"
                    : "=r"(fA[mi][0]), "=r"(fA[mi][1]), "=r"(fA[mi][2]), "=r"(fA[mi][3])
                    : "r"(ad));
            }
#pragma unroll
            for (int p = 0; p < 4; p++) {
                const int r = wn + p * 16 + b_row;
                const unsigned bd = stb + TILEB + SWOFF(r, cb);
                asm volatile("ldmatrix.sync.aligned.m8n8.x4.shared.b16 {%0,%1,%2,%3}, [%4];"
                    : "=r"(fB[2*p][0]), "=r"(fB[2*p][1]), "=r"(fB[2*p+1][0]), "=r"(fB[2*p+1][1])
                    : "r"(bd));
            }

#define MMA(d, a, b)                                                           \
    asm volatile("mma.sync.aligned.m16n8k16.row.col.f32.f16.f16.f32 "          \
                 "{%0,%1,%2,%3}, {%4,%5,%6,%7}, {%8,%9}, {%0,%1,%2,%3};"       \
                 : "+f"((d)[0]), "+f"((d)[1]), "+f"((d)[2]), "+f"((d)[3])      \
                 : "r"((a)[0]), "r"((a)[1]), "r"((a)[2]), "r"((a)[3]),         \
                   "r"((b)[0]), "r"((b)[1]))

#pragma unroll
            for (int ni = 0; ni < 8; ni++)
#pragma unroll
                for (int mi = 0; mi < 2; mi++)
                    MMA(acc[mi][ni], fA[mi], fB[ni]);
#undef MMA
        }
    }

    // epilogue
#pragma unroll
    for (int mi = 0; mi < 2; mi++) {
        const int row = bm + wm + mi * 16 + g;
#pragma unroll
        for (int ni = 0; ni < 8; ni++) {
            const int col = bn + wn + ni * 8 + tg * 2;
            if (col < N) {
                const float bx = bias[col], by = bias[col + 1];
                float2 v0 = make_float2(acc[mi][ni][0] + bx, acc[mi][ni][1] + by);
                float2 v1 = make_float2(acc[mi][ni][2] + bx, acc[mi][ni][3] + by);
                *(float2*)(C + (size_t)row * N + col)       = v0;
                *(float2*)(C + (size_t)(row + 8) * N + col) = v1;
            }
        }
    }
#undef ISSUE_STAGE
#undef SWOFF
}

// ---------------------------------------------------------------------------
// Fused RoPE: q heads (cols 0..4095) + k heads (cols 4096..4607), in-place.
// ---------------------------------------------------------------------------
__global__ void rope_all(float* __restrict__ t, const float* __restrict__ rope)
{
    const int idx = blockIdx.x * blockDim.x + threadIdx.x;
    const int total = SEQ * (NH + NKV) * 32;
    if (idx >= total) return;
    const int d  = idx & 31;
    const int hh = (idx >> 5) % (NH + NKV);
    const int s  = idx / (32 * (NH + NKV));
    const int coff = (hh < NH) ? hh * HD : KOFF + (hh - NH) * HD;

    const float c1 = rope[s * 128 + d];
    const float c2 = rope[s * 128 + d + 32];
    const float s1 = rope[s * 128 + 64 + d];
    const float s2 = rope[s * 128 + 96 + d];

    float* base = t + (size_t)s * QKVN + coff;
    const float x1 = base[d];
    const float x2 = base[d + 32];
    base[d]      = x1 * c1 - x2 * s1;
    base[d + 32] = x2 * c2 + x1 * s2;
}

// ---------------------------------------------------------------------------
// smem-staged sliding-window attention + sink gating, query-inner blocked.
// K staged fp32 (rotated chunks); V staged fp16 (halves V-loop LDS bytes).
// Lane owns dims {2*lane, 2*lane+1} for the V/output phase -> half2 I/O.
// CTA = (head, 32 queries); warp = 4 queries processed together.
// ---------------------------------------------------------------------------
#define JMAX 160
// sK: 160*64 f32 (40960B) | sV16: 160*64 f16 (20480B) | shq: 8*4*64 f32
// (8192B) | shp: 8*160*4 f32 (20480B)  => 90112B
#define ASMEM_BYTES (JMAX*64*4 + JMAX*64*2 + 8*4*64*4 + 8*JMAX*4*4)

__global__ __launch_bounds__(256, 2) void attn_kernel(
    const float* __restrict__ qkv, const float* __restrict__ sinks,
    f16* __restrict__ o16)
{
    extern __shared__ char asmc_[];
    float* sK   = (float*)asmc_;                         // [160][64] f32 rotated
    f16*   sV16 = (f16*)(asmc_ + JMAX * 64 * 4);         // [160][64] f16 plain
    float* shq  = (float*)(asmc_ + JMAX * 64 * 4 + JMAX * 64 * 2);  // [8][4][64]
    float* shp  = shq + 8 * 4 * 64;                      // [8][160][4]

    const float scale = 0.16832169945461f;  // (0.1*ln(32)+1)/8
    const int tid  = threadIdx.x;
    const int w    = tid >> 5;
    const int lane = tid & 31;
    const int h    = blockIdx.x >> 6;
    const int ib   = blockIdx.x & 63;
    const int i0   = ib * 32;
    const int kvh  = h >> 3;

    int jmin = i0 - (WINDOW - 1); if (jmin < 0) jmin = 0;
    const int jcnt = i0 + 31 - jmin + 1;   // <= 159

    // stage K (fp32, rotated 16B chunks) and V (fp16, plain)
    for (int idx = tid; idx < jcnt * 16; idx += 256) {
        const int row = idx >> 4, c4 = idx & 15;
        const size_t rb = (size_t)(jmin + row) * QKVN + kvh * HD;
        *(float4*)(sK + row * 64 + (((c4 + row) & 15) << 2)) =
            *(const float4*)(qkv + rb + KOFF + c4 * 4);
        const float4 vv = *(const float4*)(qkv + rb + VOFF + c4 * 4);
        __half2 h0 = __halves2half2(__float2half_rn(vv.x), __float2half_rn(vv.y));
        __half2 h1 = __halves2half2(__float2half_rn(vv.z), __float2half_rn(vv.w));
        unsigned* dst = (unsigned*)(sV16 + row * 64 + c4 * 4);
        dst[0] = *(unsigned*)&h0;
        dst[1] = *(unsigned*)&h1;
    }

    // stage this warp's 4 queries
    const int iw = i0 + w * 4;
    float* q_ = shq + w * 256;
#pragma unroll
    for (int qi = 0; qi < 4; qi++) {
        const float* qrow = qkv + (size_t)(iw + qi) * QKVN + h * HD;
        q_[qi * 64 + lane]      = qrow[lane];
        q_[qi * 64 + lane + 32] = qrow[lane + 32];
    }
    __syncthreads();

    int wlo = iw - (WINDOW - 1); if (wlo < 0) wlo = 0;
    const int cntw = iw + 3 - wlo + 1;     // <= 131
    const int roff = wlo - jmin;           // >= 0

    int rr[5]; bool inb[5];
#pragma unroll
    for (int t = 0; t < 5; t++) {
        const int jj = lane + 32 * t;
        inb[t] = (jj < cntw);
        int r = roff + jj;
        if (r > JMAX - 1) r = JMAX - 1;
        rr[t] = r;
    }

    // scores: read each K float4 once, FMA into 4 queries
    float dot[5][4];
#pragma unroll
    for (int t = 0; t < 5; t++)
#pragma unroll
        for (int qi = 0; qi < 4; qi++) dot[t][qi] = 0.f;

#pragma unroll
    for (int d4 = 0; d4 < 16; d4++) {
        float4 qv[4];
#pragma unroll
        for (int qi = 0; qi < 4; qi++)
            qv[qi] = *(const float4*)(q_ + qi * 64 + d4 * 4);
#pragma unroll
        for (int t = 0; t < 5; t++) {
            const int r = rr[t];
            const float4 kk = *(const float4*)(sK + r * 64 + (((d4 + r) & 15) << 2));
#pragma unroll
            for (int qi = 0; qi < 4; qi++) {
                dot[t][qi] = fmaf(kk.x, qv[qi].x, dot[t][qi]);
                dot[t][qi] = fmaf(kk.y, qv[qi].y, dot[t][qi]);
                dot[t][qi] = fmaf(kk.z, qv[qi].z, dot[t][qi]);
                dot[t][qi] = fmaf(kk.w, qv[qi].w, dot[t][qi]);
            }
        }
    }

    // per-query masked softmax + sink gating
    const float snk = sinks[h];
#pragma unroll
    for (int qi = 0; qi < 4; qi++) {
        const int i = iw + qi;
        float s[5];
#pragma unroll
        for (int t = 0; t < 5; t++) {
            const int j = wlo + lane + 32 * t;
            const bool v = inb[t] && (j <= i) && (j >= i - (WINDOW - 1));
            s[t] = v ? dot[t][qi] * scale : -1e30f;
        }
        float m = fmaxf(fmaxf(fmaxf(s[0], s[1]), fmaxf(s[2], s[3])), s[4]);
#pragma unroll
        for (int o = 16; o; o >>= 1) m = fmaxf(m, __shfl_xor_sync(0xffffffffu, m, o));
        float sum = 0.f;
#pragma unroll
        for (int t = 0; t < 5; t++) { s[t] = expf(s[t] - m); sum += s[t]; }
#pragma unroll
        for (int o = 16; o; o >>= 1) sum += __shfl_xor_sync(0xffffffffu, sum, o);
        const float lse = m + logf(sum);
        const float wsc = (1.f / (1.f + expf(snk - lse))) / sum;
#pragma unroll
        for (int t = 0; t < 5; t++) dot[t][qi] = s[t] * wsc;
    }

    // pack p: shp[w][jrel][qi] (invalid rows are exact zeros)
    float* p_ = shp + w * (JMAX * 4);
#pragma unroll
    for (int t = 0; t < 5; t++) {
        const int jj = lane + 32 * t;
        *(float4*)(p_ + jj * 4) =
            make_float4(dot[t][0], dot[t][1], dot[t][2], dot[t][3]);
    }
    __syncwarp();

    // V accumulate: lane owns dims {2*lane, 2*lane+1}; one half2 load per row
    float a[4][2];
#pragma unroll
    for (int qi = 0; qi < 4; qi++) { a[qi][0] = 0.f; a[qi][1] = 0.f; }

    const f16* vb0 = sV16 + roff * 64 + 2 * lane;
    for (int jrel = 0; jrel < cntw; jrel++) {
        const float4 p4 = *(const float4*)(p_ + jrel * 4);
        const float2 v = __half22float2(*(const __half2*)(vb0 + jrel * 64));
        a[0][0] = fmaf(p4.x, v.x, a[0][0]); a[0][1] = fmaf(p4.x, v.y, a[0][1]);
        a[1][0] = fmaf(p4.y, v.x, a[1][0]); a[1][1] = fmaf(p4.y, v.y, a[1][1]);
        a[2][0] = fmaf(p4.z, v.x, a[2][0]); a[2][1] = fmaf(p4.z, v.y, a[2][1]);
        a[3][0] = fmaf(p4.w, v.x, a[3][0]); a[3][1] = fmaf(p4.w, v.y, a[3][1]);
    }

#pragma unroll
    for (int qi = 0; qi < 4; qi++) {
        const size_t ob = (size_t)(iw + qi) * QDIM + h * HD;
        __half2 o2 = __halves2half2(__float2half_rn(a[qi][0]),
                                    __float2half_rn(a[qi][1]));
        *(__half2*)(o16 + ob + 2 * lane) = o2;
    }
}

// ---------------------------------------------------------------------------
extern "C" void kernel_launch(void* const* d_in, const int* in_sizes, int n_in,
                              void* d_out, int out_size)
{
    const float* x     = (const float*)d_in[0];
    const float* rope  = (const float*)d_in[1];
    const float* wq_w  = (const float*)d_in[2];
    const float* wq_b  = (const float*)d_in[3];
    const float* wk_w  = (const float*)d_in[4];
    const float* wk_b  = (const float*)d_in[5];
    const float* wv_w  = (const float*)d_in[6];
    const float* wv_b  = (const float*)d_in[7];
    const float* wo_w  = (const float*)d_in[8];
    const float* wo_b  = (const float*)d_in[9];
    const float* sinks = (const float*)d_in[10];
    float* out = (float*)d_out;

    float *qkv, *bqkv;
    cudaGetSymbolAddress((void**)&qkv,  g_qkv);
    cudaGetSymbolAddress((void**)&bqkv, g_bqkv);

    f16 *x16, *wc, *wo, *a16;
    cudaGetSymbolAddress((void**)&x16, g_x16);
    cudaGetSymbolAddress((void**)&wc, g_wc); cudaGetSymbolAddress((void**)&wo, g_wo);
    cudaGetSymbolAddress((void**)&a16, g_a16);

    cudaFuncSetAttribute(gemm_f16, cudaFuncAttributeMaxDynamicSharedMemorySize,
                         GSMEM_BYTES);
    cudaFuncSetAttribute(attn_kernel, cudaFuncAttributeMaxDynamicSharedMemorySize,
                         ASMEM_BYTES);

    // fused prep
    prep<<<(unsigned)((PREP_THREADS + 255) / 256), 256>>>(
        x, wq_w, wk_w, wv_w, wo_w, wq_b, wk_b, wv_b,
        x16, wc, wo, bqkv);

    // fused QKV projection: [2048 x 5120], 640 CTAs (R11 config)
    gemm_f16<<<dim3(QKVN / 128, SEQ / 128), 256, GSMEM_BYTES>>>(
        x16, wc, bqkv, qkv, SEQ, QKVN, DIM);

    // fused RoPE (q + k)
    rope_all<<<(SEQ * (NH + NKV) * 32 + 255) / 256, 256>>>(qkv, rope);

    // query-inner blocked attention (fp16 V staging)
    attn_kernel<<<NH * (SEQ / 32), 256, ASMEM_BYTES>>>(qkv, sinks, a16);

    // O-projection
    gemm_f16<<<dim3((DIM + 127) / 128, SEQ / 128), 256, GSMEM_BYTES>>>(
        a16, wo, wo_b, out, SEQ, DIM, QDIM);
}

// round 15
// speedup vs baseline: 1.1639x; 1.0037x over previous
#include <cuda_runtime.h>
#include <cuda_fp16.h>
#include <math.h>

#define SEQ 2048
#define DIM 2880
#define NH 64
#define NKV 8
#define HD 64
#define QDIM (NH*HD)     // 4096
#define KVDIM (NKV*HD)   // 512
#define QKVN 5120        // 4096 + 512 + 512
#define KOFF 4096
#define VOFF 4608
#define WINDOW 128

typedef __half f16;

// fp32 scratch
__device__ float g_qkv[SEQ * QKVN];    // 40 MB: q | k | v per row
__device__ float g_bqkv[QKVN];

// fp16 operand scratch
__device__ f16 g_x16[SEQ * DIM];       // x (fp16)
__device__ f16 g_wc[QKVN * DIM];       // concat wq|wk|wv (fp16)
__device__ f16 g_wo[DIM * QDIM];       // wo (fp16)
__device__ f16 g_a16[SEQ * QDIM];      // attn out (fp16)

// ---------------------------------------------------------------------------
// Fused prep: x -> fp16, wq/wk/wv -> wc fp16, wo -> fp16, bias concat.
// ---------------------------------------------------------------------------
#define R0 (SEQ*DIM/8)
#define R1 (QDIM*DIM/8)
#define R2 (KVDIM*DIM/8)
#define R3 (KVDIM*DIM/8)
#define R4 ((size_t)DIM*QDIM/8)
#define R5 (QKVN/8)
#define PREP_THREADS (R0+R1+R2+R3+R4+R5)

__device__ __forceinline__ void conv8(const float* __restrict__ s, f16* __restrict__ d) {
    float4 a = *(const float4*)s;
    float4 b = *(const float4*)(s + 4);
    __half2 hh[4];
    hh[0] = __halves2half2(__float2half_rn(a.x), __float2half_rn(a.y));
    hh[1] = __halves2half2(__float2half_rn(a.z), __float2half_rn(a.w));
    hh[2] = __halves2half2(__float2half_rn(b.x), __float2half_rn(b.y));
    hh[3] = __halves2half2(__float2half_rn(b.z), __float2half_rn(b.w));
    *(uint4*)d = *(uint4*)hh;
}

__global__ void prep(const float* __restrict__ x,
                     const float* __restrict__ wq, const float* __restrict__ wk,
                     const float* __restrict__ wv, const float* __restrict__ wo,
                     const float* __restrict__ qb, const float* __restrict__ kb,
                     const float* __restrict__ vb,
                     f16* __restrict__ x16,
                     f16* __restrict__ wc, f16* __restrict__ wo16,
                     float* __restrict__ bqkv)
{
    long t = (long)blockIdx.x * blockDim.x + threadIdx.x;
    if (t < (long)R0) { conv8(x + t * 8, x16 + t * 8); return; }
    t -= R0;
    if (t < (long)R1) { conv8(wq + t * 8, wc + t * 8); return; }
    t -= R1;
    if (t < (long)R2) { conv8(wk + t * 8, wc + (size_t)KOFF * DIM + t * 8); return; }
    t -= R2;
    if (t < (long)R3) { conv8(wv + t * 8, wc + (size_t)VOFF * DIM + t * 8); return; }
    t -= R3;
    if (t < (long)R4) { conv8(wo + t * 8, wo16 + t * 8); return; }
    t -= R4;
    if (t < (long)R5) {
        const int i = (int)t * 8;
#pragma unroll
        for (int j = 0; j < 8; j++) {
            const int c = i + j;
            bqkv[c] = (c < KOFF) ? qb[c] : (c < VOFF ? kb[c - KOFF] : vb[c - VOFF]);
        }
    }
}

// ---------------------------------------------------------------------------
// fp16 mma.sync GEMM (NT): C = A*B^T + bias   [R11-proven config]
// Block 128x128, BK=64, 3-stage cp.async ring, SW128-swizzled 128B rows,
// 256 thr = 8 warps (4m x 2n), warp tile 32x64. 2 CTAs/SM (192KB smem).
// ---------------------------------------------------------------------------
#define TILEB 16384u                // one operand tile: 128 rows x 128 bytes
#define STAGEB (2u*TILEB)           // A, B = 32 KB
#define NSTG 3
#define GSMEM_BYTES (NSTG*STAGEB)   // 96 KB

__device__ __forceinline__ void cpa16(unsigned dst, const void* src) {
    asm volatile("cp.async.cg.shared.global [%0], [%1], 16;" :: "r"(dst), "l"(src));
}
__device__ __forceinline__ void cpa16p(unsigned dst, const void* src, int sz) {
    asm volatile("cp.async.cg.shared.global [%0], [%1], 16, %2;"
                 :: "r"(dst), "l"(src), "r"(sz));
}

__global__ __launch_bounds__(256, 2) void gemm_f16(
    const f16* __restrict__ A, const f16* __restrict__ B,
    const float* __restrict__ bias, float* __restrict__ C,
    int M, int N, int K)
{
    extern __shared__ char dsm[];
    unsigned sb;
    { unsigned long long t = __cvta_generic_to_shared(dsm); sb = (unsigned)t; }

    const int tid  = threadIdx.x;
    const int wid  = tid >> 5;
    const int lane = tid & 31;
    const int bm   = blockIdx.y * 128;
    const int bn   = blockIdx.x * 128;
    const int wm   = (wid & 3) * 32;
    const int wn   = (wid >> 2) * 64;
    const int g    = lane >> 2;
    const int tg   = lane & 3;

    const int KT = K / 64;

    const int r0c = tid >> 3;            // base row 0..31 (stride 32)
    const int c0c = tid & 7;             // 16B segment 0..7

#define SWOFF(r, c) ((unsigned)((r) * 128 + ((((c) ^ ((r) & 7))) << 4)))

#define ISSUE_STAGE(sidx, k0)                                                  \
    do {                                                                       \
        const unsigned tb = sb + (unsigned)(sidx) * STAGEB;                    \
        _Pragma("unroll")                                                      \
        for (int it = 0; it < 4; it++) {                                       \
            const int r = r0c + it * 32;                                       \
            const unsigned so = SWOFF(r, c0c);                                 \
            const size_t ao = (size_t)(bm + r) * K + (k0) + c0c * 8;           \
            const int brw = bn + r;                                            \
            const int pz  = (brw < N) ? 16 : 0;                                \
            const size_t bo = (size_t)((brw < N) ? brw : 0) * K + (k0) + c0c * 8; \
            cpa16 (tb + so,         A + ao);                                   \
            cpa16p(tb + TILEB + so, B + bo, pz);                               \
        }                                                                      \
        asm volatile("cp.async.commit_group;");                                \
    } while (0)

    float acc[2][8][4];
#pragma unroll
    for (int mi = 0; mi < 2; mi++)
#pragma unroll
        for (int ni = 0; ni < 8; ni++)
#pragma unroll
            for (int r = 0; r < 4; r++) acc[mi][ni][r] = 0.f;

    ISSUE_STAGE(0, 0);
    ISSUE_STAGE(1, 64);

    const int a_row = ((lane >> 3) & 1) * 8 + (lane & 7);
    const int a_ch  = (lane >> 4) & 1;
    const int b_row = ((lane >> 4) & 1) * 8 + (lane & 7);
    const int b_ch  = (lane >> 3) & 1;

    for (int kt = 0; kt < KT; kt++) {
        asm volatile("cp.async.wait_group %0;" :: "n"(1));
        __syncthreads();

        if (kt + 2 < KT) ISSUE_STAGE((kt + 2) % NSTG, (kt + 2) * 64);
        else             asm volatile("cp.async.commit_group;");

        const unsigned stb = sb + (unsigned)(kt % NSTG) * STAGEB;

#pragma unroll
        for (int ks = 0; ks < 4; ks++) {
            unsigned fA[2][4], fB[8][2];
            const int ca = ks * 2 + a_ch;
            const int cb = ks * 2 + b_ch;

#pragma unroll
            for (int mi = 0; mi < 2; mi++) {
                const int r = wm + mi * 16 + a_row;
                const unsigned ad = stb + SWOFF(r, ca);
                asm volatile("ldmatrix.sync.aligned.m8n8.x4.shared.b16 {%0,%1,%2,%3}, [%4];"
                    : "=r"(fA[mi][0]), "=r"(fA[mi][1]), "=r"(fA[mi][2]), "=r"(fA[mi][3])
                    : "r"(ad));
            }
#pragma unroll
            for (int p = 0; p < 4; p++) {
                const int r = wn + p * 16 + b_row;
                const unsigned bd = stb + TILEB + SWOFF(r, cb);
                asm volatile("ldmatrix.sync.aligned.m8n8.x4.shared.b16 {%0,%1,%2,%3}, [%4];"
                    : "=r"(fB[2*p][0]), "=r"(fB[2*p][1]), "=r"(fB[2*p+1][0]), "=r"(fB[2*p+1][1])
                    : "r"(bd));
            }

#define MMA(d, a, b)                                                           \
    asm volatile("mma.sync.aligned.m16n8k16.row.col.f32.f16.f16.f32 "          \
                 "{%0,%1,%2,%3}, {%4,%5,%6,%7}, {%8,%9}, {%0,%1,%2,%3};"       \
                 : "+f"((d)[0]), "+f"((d)[1]), "+f"((d)[2]), "+f"((d)[3])      \
                 : "r"((a)[0]), "r"((a)[1]), "r"((a)[2]), "r"((a)[3]),         \
                   "r"((b)[0]), "r"((b)[1]))

#pragma unroll
            for (int ni = 0; ni < 8; ni++)
#pragma unroll
                for (int mi = 0; mi < 2; mi++)
                    MMA(acc[mi][ni], fA[mi], fB[ni]);
#undef MMA
        }
    }

    // epilogue
#pragma unroll
    for (int mi = 0; mi < 2; mi++) {
        const int row = bm + wm + mi * 16 + g;
#pragma unroll
        for (int ni = 0; ni < 8; ni++) {
            const int col = bn + wn + ni * 8 + tg * 2;
            if (col < N) {
                const float bx = bias[col], by = bias[col + 1];
                float2 v0 = make_float2(acc[mi][ni][0] + bx, acc[mi][ni][1] + by);
                float2 v1 = make_float2(acc[mi][ni][2] + bx, acc[mi][ni][3] + by);
                *(float2*)(C + (size_t)row * N + col)       = v0;
                *(float2*)(C + (size_t)(row + 8) * N + col) = v1;
            }
        }
    }
#undef ISSUE_STAGE
#undef SWOFF
}

// ---------------------------------------------------------------------------
// Fused RoPE: q heads (cols 0..4095) + k heads (cols 4096..4607), in-place.
// ---------------------------------------------------------------------------
__global__ void rope_all(float* __restrict__ t, const float* __restrict__ rope)
{
    const int idx = blockIdx.x * blockDim.x + threadIdx.x;
    const int total = SEQ * (NH + NKV) * 32;
    if (idx >= total) return;
    const int d  = idx & 31;
    const int hh = (idx >> 5) % (NH + NKV);
    const int s  = idx / (32 * (NH + NKV));
    const int coff = (hh < NH) ? hh * HD : KOFF + (hh - NH) * HD;

    const float c1 = rope[s * 128 + d];
    const float c2 = rope[s * 128 + d + 32];
    const float s1 = rope[s * 128 + 64 + d];
    const float s2 = rope[s * 128 + 96 + d];

    float* base = t + (size_t)s * QKVN + coff;
    const float x1 = base[d];
    const float x2 = base[d + 32];
    base[d]      = x1 * c1 - x2 * s1;
    base[d + 32] = x2 * c2 + x1 * s2;
}

// ---------------------------------------------------------------------------
// Fast exp for softmax: exp(x) with x <= 0 (or -1e30 masked), via exp2
// magic-number rounding + degree-5 poly. All FMA/ALU pipe, no MUFU.
// ---------------------------------------------------------------------------
__device__ __forceinline__ float fexp(float y /* = x * log2(e) */)
{
    y = fmaxf(y, -126.f);
    const float r  = y + 12582912.f;          // round-to-nearest via magic
    const float nf = r - 12582912.f;
    const float f  = y - nf;
    float p = 1.3276472e-3f;
    p = fmaf(p, f, 9.6180289e-3f);
    p = fmaf(p, f, 5.5504109e-2f);
    p = fmaf(p, f, 2.4022651e-1f);
    p = fmaf(p, f, 6.9314718e-1f);
    p = fmaf(p, f, 1.0f);
    const int ni = __float_as_int(r) - 0x4B400000;       // n as int
    const float sc = __int_as_float((ni + 127) << 23);   // 2^n
    return p * sc;
}

// ---------------------------------------------------------------------------
// smem-staged sliding-window attention + sink gating, query-inner blocked.
// [R11-proven layout: fp32 K (rotated) + fp32 V (plain)] + FMA-pipe softmax.
// CTA = (head, 32 queries); warp = 4 queries processed together.
// ---------------------------------------------------------------------------
#define JMAX 160
#define ASMEM_FLOATS (2*JMAX*64 + 8*4*64 + 8*JMAX*4)  // sK, sV, shq, shp
#define ASMEM_BYTES  (ASMEM_FLOATS*4)                 // 110592

__global__ __launch_bounds__(256, 2) void attn_kernel(
    const float* __restrict__ qkv, const float* __restrict__ sinks,
    f16* __restrict__ o16)
{
    extern __shared__ float asm_[];
    float* sK  = asm_;                    // [160][64], rotated 16B chunks
    float* sV  = asm_ + JMAX * 64;        // [160][64], plain
    float* shq = asm_ + 2 * JMAX * 64;    // [8][4][64]
    float* shp = shq + 8 * 4 * 64;        // [8][160][4]

    const float scale = 0.16832169945461f;  // (0.1*ln(32)+1)/8
    const float L2E   = 1.44269504089f;
    const int tid  = threadIdx.x;
    const int w    = tid >> 5;
    const int lane = tid & 31;
    const int h    = blockIdx.x >> 6;
    const int ib   = blockIdx.x & 63;
    const int i0   = ib * 32;
    const int kvh  = h >> 3;

    int jmin = i0 - (WINDOW - 1); if (jmin < 0) jmin = 0;
    const int jcnt = i0 + 31 - jmin + 1;   // <= 159

    for (int idx = tid; idx < jcnt * 16; idx += 256) {
        const int row = idx >> 4, c4 = idx & 15;
        const size_t rb = (size_t)(jmin + row) * QKVN + kvh * HD;
        *(float4*)(sK + row * 64 + (((c4 + row) & 15) << 2)) =
            *(const float4*)(qkv + rb + KOFF + c4 * 4);
        *(float4*)(sV + row * 64 + (c4 << 2)) =
            *(const float4*)(qkv + rb + VOFF + c4 * 4);
    }

    const int iw = i0 + w * 4;
    float* q_ = shq + w * 256;
#pragma unroll
    for (int qi = 0; qi < 4; qi++) {
        const float* qrow = qkv + (size_t)(iw + qi) * QKVN + h * HD;
        q_[qi * 64 + lane]      = qrow[lane];
        q_[qi * 64 + lane + 32] = qrow[lane + 32];
    }
    __syncthreads();

    int wlo = iw - (WINDOW - 1); if (wlo < 0) wlo = 0;
    const int cntw = iw + 3 - wlo + 1;     // <= 131
    const int roff = wlo - jmin;           // >= 0

    int rr[5]; bool inb[5];
#pragma unroll
    for (int t = 0; t < 5; t++) {
        const int jj = lane + 32 * t;
        inb[t] = (jj < cntw);
        int r = roff + jj;
        if (r > JMAX - 1) r = JMAX - 1;
        rr[t] = r;
    }

    float dot[5][4];
#pragma unroll
    for (int t = 0; t < 5; t++)
#pragma unroll
        for (int qi = 0; qi < 4; qi++) dot[t][qi] = 0.f;

#pragma unroll
    for (int d4 = 0; d4 < 16; d4++) {
        float4 qv[4];
#pragma unroll
        for (int qi = 0; qi < 4; qi++)
            qv[qi] = *(const float4*)(q_ + qi * 64 + d4 * 4);
#pragma unroll
        for (int t = 0; t < 5; t++) {
            const int r = rr[t];
            const float4 kk = *(const float4*)(sK + r * 64 + (((d4 + r) & 15) << 2));
#pragma unroll
            for (int qi = 0; qi < 4; qi++) {
                dot[t][qi] = fmaf(kk.x, qv[qi].x, dot[t][qi]);
                dot[t][qi] = fmaf(kk.y, qv[qi].y, dot[t][qi]);
                dot[t][qi] = fmaf(kk.z, qv[qi].z, dot[t][qi]);
                dot[t][qi] = fmaf(kk.w, qv[qi].w, dot[t][qi]);
            }
        }
    }

    const float snk = sinks[h];
#pragma unroll
    for (int qi = 0; qi < 4; qi++) {
        const int i = iw + qi;
        float s[5];
#pragma unroll
        for (int t = 0; t < 5; t++) {
            const int j = wlo + lane + 32 * t;
            const bool v = inb[t] && (j <= i) && (j >= i - (WINDOW - 1));
            s[t] = v ? dot[t][qi] * scale : -1e30f;
        }
        float m = fmaxf(fmaxf(fmaxf(s[0], s[1]), fmaxf(s[2], s[3])), s[4]);
#pragma unroll
        for (int o = 16; o; o >>= 1) m = fmaxf(m, __shfl_xor_sync(0xffffffffu, m, o));

        const float ml = m * L2E;
        float sum = 0.f;
#pragma unroll
        for (int t = 0; t < 5; t++) {
            s[t] = fexp(fmaf(s[t], L2E, -ml));   // FMA-pipe exp
            sum += s[t];
        }
#pragma unroll
        for (int o = 16; o; o >>= 1) sum += __shfl_xor_sync(0xffffffffu, sum, o);
        const float lse = m + logf(sum);
        const float wsc = (1.f / (1.f + expf(snk - lse))) / sum;
#pragma unroll
        for (int t = 0; t < 5; t++) dot[t][qi] = s[t] * wsc;
    }

    float* p_ = shp + w * (JMAX * 4);
#pragma unroll
    for (int t = 0; t < 5; t++) {
        const int jj = lane + 32 * t;
        *(float4*)(p_ + jj * 4) =
            make_float4(dot[t][0], dot[t][1], dot[t][2], dot[t][3]);
    }
    __syncwarp();

    float a[4][2];
#pragma unroll
    for (int qi = 0; qi < 4; qi++) { a[qi][0] = 0.f; a[qi][1] = 0.f; }

    const float* vb0 = sV + roff * 64;
    for (int jrel = 0; jrel < cntw; jrel++) {
        const float4 p4 = *(const float4*)(p_ + jrel * 4);
        const float v0 = vb0[jrel * 64 + lane];
        const float v1 = vb0[jrel * 64 + lane + 32];
        a[0][0] = fmaf(p4.x, v0, a[0][0]); a[0][1] = fmaf(p4.x, v1, a[0][1]);
        a[1][0] = fmaf(p4.y, v0, a[1][0]); a[1][1] = fmaf(p4.y, v1, a[1][1]);
        a[2][0] = fmaf(p4.z, v0, a[2][0]); a[2][1] = fmaf(p4.z, v1, a[2][1]);
        a[3][0] = fmaf(p4.w, v0, a[3][0]); a[3][1] = fmaf(p4.w, v1, a[3][1]);
    }

#pragma unroll
    for (int qi = 0; qi < 4; qi++) {
        const size_t ob = (size_t)(iw + qi) * QDIM + h * HD;
        o16[ob + lane]      = __float2half_rn(a[qi][0]);
        o16[ob + lane + 32] = __float2half_rn(a[qi][1]);
    }
}

// ---------------------------------------------------------------------------
extern "C" void kernel_launch(void* const* d_in, const int* in_sizes, int n_in,
                              void* d_out, int out_size)
{
    const float* x     = (const float*)d_in[0];
    const float* rope  = (const float*)d_in[1];
    const float* wq_w  = (const float*)d_in[2];
    const float* wq_b  = (const float*)d_in[3];
    const float* wk_w  = (const float*)d_in[4];
    const float* wk_b  = (const float*)d_in[5];
    const float* wv_w  = (const float*)d_in[6];
    const float* wv_b  = (const float*)d_in[7];
    const float* wo_w  = (const float*)d_in[8];
    const float* wo_b  = (const float*)d_in[9];
    const float* sinks = (const float*)d_in[10];
    float* out = (float*)d_out;

    float *qkv, *bqkv;
    cudaGetSymbolAddress((void**)&qkv,  g_qkv);
    cudaGetSymbolAddress((void**)&bqkv, g_bqkv);

    f16 *x16, *wc, *wo, *a16;
    cudaGetSymbolAddress((void**)&x16, g_x16);
    cudaGetSymbolAddress((void**)&wc, g_wc); cudaGetSymbolAddress((void**)&wo, g_wo);
    cudaGetSymbolAddress((void**)&a16, g_a16);

    cudaFuncSetAttribute(gemm_f16, cudaFuncAttributeMaxDynamicSharedMemorySize,
                         GSMEM_BYTES);
    cudaFuncSetAttribute(attn_kernel, cudaFuncAttributeMaxDynamicSharedMemorySize,
                         ASMEM_BYTES);

    // fused prep
    prep<<<(unsigned)((PREP_THREADS + 255) / 256), 256>>>(
        x, wq_w, wk_w, wv_w, wo_w, wq_b, wk_b, wv_b,
        x16, wc, wo, bqkv);

    // fused QKV projection: [2048 x 5120], 640 CTAs
    gemm_f16<<<dim3(QKVN / 128, SEQ / 128), 256, GSMEM_BYTES>>>(
        x16, wc, bqkv, qkv, SEQ, QKVN, DIM);

    // fused RoPE (q + k)
    rope_all<<<(SEQ * (NH + NKV) * 32 + 255) / 256, 256>>>(qkv, rope);

    // query-inner blocked attention (FMA-pipe softmax exp)
    attn_kernel<<<NH * (SEQ / 32), 256, ASMEM_BYTES>>>(qkv, sinks, a16);

    // O-projection
    gemm_f16<<<dim3((DIM + 127) / 128, SEQ / 128), 256, GSMEM_BYTES>>>(
        a16, wo, wo_b, out, SEQ, DIM, QDIM);
}

// round 16
// speedup vs baseline: 1.5567x; 1.3374x over previous
#include <cuda_runtime.h>
#include <cuda_fp16.h>
#include <math.h>

#define SEQ 2048
#define DIM 2880
#define NH 64
#define NKV 8
#define HD 64
#define QDIM (NH*HD)     // 4096
#define KVDIM (NKV*HD)   // 512
#define QKVN 5120        // 4096 + 512 + 512
#define KOFF 4096
#define VOFF 4608
#define WINDOW 128

typedef __half f16;

// fp32 scratch
__device__ float g_qkv[SEQ * QKVN];    // 40 MB: q | k | v per row
__device__ float g_bqkv[QKVN];

// fp16 operand scratch
__device__ f16 g_x16[SEQ * DIM];       // x (fp16)
__device__ f16 g_wc[QKVN * DIM];       // concat wq|wk|wv (fp16)
__device__ f16 g_wo[DIM * QDIM];       // wo (fp16)
__device__ f16 g_a16[SEQ * QDIM];      // attn out (fp16)

// ---------------------------------------------------------------------------
// Fused prep: x -> fp16, wq/wk/wv -> wc fp16, wo -> fp16, bias concat.
// ---------------------------------------------------------------------------
#define R0 (SEQ*DIM/8)
#define R1 (QDIM*DIM/8)
#define R2 (KVDIM*DIM/8)
#define R3 (KVDIM*DIM/8)
#define R4 ((size_t)DIM*QDIM/8)
#define R5 (QKVN/8)
#define PREP_THREADS (R0+R1+R2+R3+R4+R5)

__device__ __forceinline__ void conv8(const float* __restrict__ s, f16* __restrict__ d) {
    float4 a = *(const float4*)s;
    float4 b = *(const float4*)(s + 4);
    __half2 hh[4];
    hh[0] = __halves2half2(__float2half_rn(a.x), __float2half_rn(a.y));
    hh[1] = __halves2half2(__float2half_rn(a.z), __float2half_rn(a.w));
    hh[2] = __halves2half2(__float2half_rn(b.x), __float2half_rn(b.y));
    hh[3] = __halves2half2(__float2half_rn(b.z), __float2half_rn(b.w));
    *(uint4*)d = *(uint4*)hh;
}

__global__ void prep(const float* __restrict__ x,
                     const float* __restrict__ wq, const float* __restrict__ wk,
                     const float* __restrict__ wv, const float* __restrict__ wo,
                     const float* __restrict__ qb, const float* __restrict__ kb,
                     const float* __restrict__ vb,
                     f16* __restrict__ x16,
                     f16* __restrict__ wc, f16* __restrict__ wo16,
                     float* __restrict__ bqkv)
{
    long t = (long)blockIdx.x * blockDim.x + threadIdx.x;
    if (t < (long)R0) { conv8(x + t * 8, x16 + t * 8); return; }
    t -= R0;
    if (t < (long)R1) { conv8(wq + t * 8, wc + t * 8); return; }
    t -= R1;
    if (t < (long)R2) { conv8(wk + t * 8, wc + (size_t)KOFF * DIM + t * 8); return; }
    t -= R2;
    if (t < (long)R3) { conv8(wv + t * 8, wc + (size_t)VOFF * DIM + t * 8); return; }
    t -= R3;
    if (t < (long)R4) { conv8(wo + t * 8, wo16 + t * 8); return; }
    t -= R4;
    if (t < (long)R5) {
        const int i = (int)t * 8;
#pragma unroll
        for (int j = 0; j < 8; j++) {
            const int c = i + j;
            bqkv[c] = (c < KOFF) ? qb[c] : (c < VOFF ? kb[c - KOFF] : vb[c - VOFF]);
        }
    }
}

// ---------------------------------------------------------------------------
// fp16 mma.sync GEMM (NT): C = A*B^T + bias   [R11-proven config]
// ---------------------------------------------------------------------------
#define TILEB 16384u
#define STAGEB (2u*TILEB)
#define NSTG 3
#define GSMEM_BYTES (NSTG*STAGEB)   // 96 KB

__device__ __forceinline__ void cpa16(unsigned dst, const void* src) {
    asm volatile("cp.async.cg.shared.global [%0], [%1], 16;" :: "r"(dst), "l"(src));
}
__device__ __forceinline__ void cpa16p(unsigned dst, const void* src, int sz) {
    asm volatile("cp.async.cg.shared.global [%0], [%1], 16, %2;"
                 :: "r"(dst), "l"(src), "r"(sz));
}

#define MMA_F16(d, a0, a1, a2, a3, b0, b1)                                     \
    asm volatile("mma.sync.aligned.m16n8k16.row.col.f32.f16.f16.f32 "          \
                 "{%0,%1,%2,%3}, {%4,%5,%6,%7}, {%8,%9}, {%0,%1,%2,%3};"       \
                 : "+f"((d)[0]), "+f"((d)[1]), "+f"((d)[2]), "+f"((d)[3])      \
                 : "r"(a0), "r"(a1), "r"(a2), "r"(a3), "r"(b0), "r"(b1))

__global__ __launch_bounds__(256, 2) void gemm_f16(
    const f16* __restrict__ A, const f16* __restrict__ B,
    const float* __restrict__ bias, float* __restrict__ C,
    int M, int N, int K)
{
    extern __shared__ char dsm[];
    unsigned sb;
    { unsigned long long t = __cvta_generic_to_shared(dsm); sb = (unsigned)t; }

    const int tid  = threadIdx.x;
    const int wid  = tid >> 5;
    const int lane = tid & 31;
    const int bm   = blockIdx.y * 128;
    const int bn   = blockIdx.x * 128;
    const int wm   = (wid & 3) * 32;
    const int wn   = (wid >> 2) * 64;
    const int g    = lane >> 2;
    const int tg   = lane & 3;

    const int KT = K / 64;
    const int r0c = tid >> 3;
    const int c0c = tid & 7;

#define SWOFF(r, c) ((unsigned)((r) * 128 + ((((c) ^ ((r) & 7))) << 4)))

#define ISSUE_STAGE(sidx, k0)                                                  \
    do {                                                                       \
        const unsigned tb = sb + (unsigned)(sidx) * STAGEB;                    \
        _Pragma("unroll")                                                      \
        for (int it = 0; it < 4; it++) {                                       \
            const int r = r0c + it * 32;                                       \
            const unsigned so = SWOFF(r, c0c);                                 \
            const size_t ao = (size_t)(bm + r) * K + (k0) + c0c * 8;           \
            const int brw = bn + r;                                            \
            const int pz  = (brw < N) ? 16 : 0;                                \
            const size_t bo = (size_t)((brw < N) ? brw : 0) * K + (k0) + c0c * 8; \
            cpa16 (tb + so,         A + ao);                                   \
            cpa16p(tb + TILEB + so, B + bo, pz);                               \
        }                                                                      \
        asm volatile("cp.async.commit_group;");                                \
    } while (0)

    float acc[2][8][4];
#pragma unroll
    for (int mi = 0; mi < 2; mi++)
#pragma unroll
        for (int ni = 0; ni < 8; ni++)
#pragma unroll
            for (int r = 0; r < 4; r++) acc[mi][ni][r] = 0.f;

    ISSUE_STAGE(0, 0);
    ISSUE_STAGE(1, 64);

    const int a_row = ((lane >> 3) & 1) * 8 + (lane & 7);
    const int a_ch  = (lane >> 4) & 1;
    const int b_row = ((lane >> 4) & 1) * 8 + (lane & 7);
    const int b_ch  = (lane >> 3) & 1;

    for (int kt = 0; kt < KT; kt++) {
        asm volatile("cp.async.wait_group %0;" :: "n"(1));
        __syncthreads();

        if (kt + 2 < KT) ISSUE_STAGE((kt + 2) % NSTG, (kt + 2) * 64);
        else             asm volatile("cp.async.commit_group;");

        const unsigned stb = sb + (unsigned)(kt % NSTG) * STAGEB;

#pragma unroll
        for (int ks = 0; ks < 4; ks++) {
            unsigned fA[2][4], fB[8][2];
            const int ca = ks * 2 + a_ch;
            const int cb = ks * 2 + b_ch;

#pragma unroll
            for (int mi = 0; mi < 2; mi++) {
                const int r = wm + mi * 16 + a_row;
                const unsigned ad = stb + SWOFF(r, ca);
                asm volatile("ldmatrix.sync.aligned.m8n8.x4.shared.b16 {%0,%1,%2,%3}, [%4];"
                    : "=r"(fA[mi][0]), "=r"(fA[mi][1]), "=r"(fA[mi][2]), "=r"(fA[mi][3])
                    : "r"(ad));
            }
#pragma unroll
            for (int p = 0; p < 4; p++) {
                const int r = wn + p * 16 + b_row;
                const unsigned bd = stb + TILEB + SWOFF(r, cb);
                asm volatile("ldmatrix.sync.aligned.m8n8.x4.shared.b16 {%0,%1,%2,%3}, [%4];"
                    : "=r"(fB[2*p][0]), "=r"(fB[2*p][1]), "=r"(fB[2*p+1][0]), "=r"(fB[2*p+1][1])
                    : "r"(bd));
            }
#pragma unroll
            for (int ni = 0; ni < 8; ni++)
#pragma unroll
                for (int mi = 0; mi < 2; mi++)
                    MMA_F16(acc[mi][ni], fA[mi][0], fA[mi][1], fA[mi][2], fA[mi][3],
                            fB[ni][0], fB[ni][1]);
        }
    }

#pragma unroll
    for (int mi = 0; mi < 2; mi++) {
        const int row = bm + wm + mi * 16 + g;
#pragma unroll
        for (int ni = 0; ni < 8; ni++) {
            const int col = bn + wn + ni * 8 + tg * 2;
            if (col < N) {
                const float bx = bias[col], by = bias[col + 1];
                float2 v0 = make_float2(acc[mi][ni][0] + bx, acc[mi][ni][1] + by);
                float2 v1 = make_float2(acc[mi][ni][2] + bx, acc[mi][ni][3] + by);
                *(float2*)(C + (size_t)row * N + col)       = v0;
                *(float2*)(C + (size_t)(row + 8) * N + col) = v1;
            }
        }
    }
#undef ISSUE_STAGE
#undef SWOFF
}

// ---------------------------------------------------------------------------
// Fused RoPE (q + k), in-place on the fp32 qkv buffer.
// ---------------------------------------------------------------------------
__global__ void rope_all(float* __restrict__ t, const float* __restrict__ rope)
{
    const int idx = blockIdx.x * blockDim.x + threadIdx.x;
    const int total = SEQ * (NH + NKV) * 32;
    if (idx >= total) return;
    const int d  = idx & 31;
    const int hh = (idx >> 5) % (NH + NKV);
    const int s  = idx / (32 * (NH + NKV));
    const int coff = (hh < NH) ? hh * HD : KOFF + (hh - NH) * HD;

    const float c1 = rope[s * 128 + d];
    const float c2 = rope[s * 128 + d + 32];
    const float s1 = rope[s * 128 + 64 + d];
    const float s2 = rope[s * 128 + 96 + d];

    float* base = t + (size_t)s * QKVN + coff;
    const float x1 = base[d];
    const float x2 = base[d + 32];
    base[d]      = x1 * c1 - x2 * s1;
    base[d + 32] = x2 * c2 + x1 * s2;
}

// ---------------------------------------------------------------------------
// FMA-pipe exp: input y = x*log2(e), x <= 0 (or masked very negative).
// ---------------------------------------------------------------------------
__device__ __forceinline__ float fexp(float y)
{
    y = fmaxf(y, -126.f);
    const float r  = y + 12582912.f;
    const float nf = r - 12582912.f;
    const float f  = y - nf;
    float p = 1.3276472e-3f;
    p = fmaf(p, f, 9.6180289e-3f);
    p = fmaf(p, f, 5.5504109e-2f);
    p = fmaf(p, f, 2.4022651e-1f);
    p = fmaf(p, f, 6.9314718e-1f);
    p = fmaf(p, f, 1.0f);
    const int ni = __float_as_int(r) - 0x4B400000;
    const float sc = __int_as_float((ni + 127) << 23);
    return p * sc;
}

// ---------------------------------------------------------------------------
// Flash-style tensor-core attention + sink gating.
// CTA = (head, 128 queries), 8 warps; warp = 16 queries (m16).
// K,V staged fp16 (swizzled 128B rows); Q staged fp16 with scale folded.
// QK^T via mma (K's [j][d] IS the col-major B); softmax on fragments;
// S fragments ARE the PV A-operand; V via ldmatrix.trans.
// ---------------------------------------------------------------------------
#define JC 256                       // staged rows (window union <= 255)
#define AQOFF (JC*128*2)             // after K and V tiles
#define ASMEM_BYTES (JC*128 + JC*128 + 128*128)   // 32KB K + 32KB V + 16KB Q = 80KB

#define ASW(r, c) ((unsigned)((r) * 128 + ((((c) ^ ((r) & 7))) << 4)))

__global__ __launch_bounds__(256, 2) void attn_kernel(
    const float* __restrict__ qkv, const float* __restrict__ sinks,
    f16* __restrict__ o16)
{
    extern __shared__ char asmc_[];
    unsigned sbase;
    { unsigned long long t = __cvta_generic_to_shared(asmc_); sbase = (unsigned)t; }
    const unsigned sK = sbase;                 // [256][64] f16 swizzled
    const unsigned sV = sbase + JC * 128;      // [256][64] f16 swizzled
    const unsigned sQ = sbase + 2 * JC * 128;  // [128][64] f16 swizzled

    const float scale = 0.16832169945461f;  // (0.1*ln(32)+1)/8
    const float L2E   = 1.44269504089f;
    const int tid  = threadIdx.x;
    const int w    = tid >> 5;
    const int lane = tid & 31;
    const int g    = lane >> 2;
    const int tg   = lane & 3;
    const int h    = blockIdx.x >> 4;        // 16 query-blocks per head
    const int ib   = blockIdx.x & 15;
    const int i0   = ib * 128;
    const int kvh  = h >> 3;

    int jmin = i0 - (WINDOW - 1); if (jmin < 0) jmin = 0;
    const int jcnt = i0 + 127 - jmin + 1;    // <= 255

    // ---- stage K, V (fp16, zero-padded rows) ----
#pragma unroll
    for (int it = 0; it < 8; it++) {
        const int idx = tid + it * 256;      // 2048 = 256 rows x 8 chunks
        const int row = idx >> 3, c = idx & 7;
        uint4 kz = make_uint4(0, 0, 0, 0), vz = make_uint4(0, 0, 0, 0);
        if (row < jcnt) {
            const size_t rb = (size_t)(jmin + row) * QKVN + kvh * HD + c * 8;
            const float4 k0 = *(const float4*)(qkv + rb + KOFF);
            const float4 k1 = *(const float4*)(qkv + rb + KOFF + 4);
            const float4 v0 = *(const float4*)(qkv + rb + VOFF);
            const float4 v1 = *(const float4*)(qkv + rb + VOFF + 4);
            __half2 a, b2, c2_, d2;
            a  = __halves2half2(__float2half_rn(k0.x), __float2half_rn(k0.y));
            b2 = __halves2half2(__float2half_rn(k0.z), __float2half_rn(k0.w));
            c2_= __halves2half2(__float2half_rn(k1.x), __float2half_rn(k1.y));
            d2 = __halves2half2(__float2half_rn(k1.z), __float2half_rn(k1.w));
            kz = make_uint4(*(unsigned*)&a, *(unsigned*)&b2, *(unsigned*)&c2_, *(unsigned*)&d2);
            a  = __halves2half2(__float2half_rn(v0.x), __float2half_rn(v0.y));
            b2 = __halves2half2(__float2half_rn(v0.z), __float2half_rn(v0.w));
            c2_= __halves2half2(__float2half_rn(v1.x), __float2half_rn(v1.y));
            d2 = __halves2half2(__float2half_rn(v1.z), __float2half_rn(v1.w));
            vz = make_uint4(*(unsigned*)&a, *(unsigned*)&b2, *(unsigned*)&c2_, *(unsigned*)&d2);
        }
        *(uint4*)(asmc_ + (sK - sbase) + ASW(row, c)) = kz;
        *(uint4*)(asmc_ + (sV - sbase) + ASW(row, c)) = vz;
    }
    // ---- stage Q (fp16, scale folded) ----
#pragma unroll
    for (int it = 0; it < 4; it++) {
        const int idx = tid + it * 256;      // 1024 = 128 rows x 8 chunks
        const int row = idx >> 3, c = idx & 7;
        const size_t rb = (size_t)(i0 + row) * QKVN + h * HD + c * 8;
        const float4 q0 = *(const float4*)(qkv + rb);
        const float4 q1 = *(const float4*)(qkv + rb + 4);
        __half2 a  = __halves2half2(__float2half_rn(q0.x * scale), __float2half_rn(q0.y * scale));
        __half2 b2 = __halves2half2(__float2half_rn(q0.z * scale), __float2half_rn(q0.w * scale));
        __half2 c2_= __halves2half2(__float2half_rn(q1.x * scale), __float2half_rn(q1.y * scale));
        __half2 d2 = __halves2half2(__float2half_rn(q1.z * scale), __float2half_rn(q1.w * scale));
        *(uint4*)(asmc_ + (sQ - sbase) + ASW(row, c)) =
            make_uint4(*(unsigned*)&a, *(unsigned*)&b2, *(unsigned*)&c2_, *(unsigned*)&d2);
    }
    __syncthreads();

    const int iw  = i0 + w * 16;
    int wlo = iw - (WINDOW - 1); if (wlo < 0) wlo = 0;
    const int jb  = wlo - jmin;              // multiple of 16

    // ---- QK^T: S[16 x 144] in fragments ----
    float S[18][4];
#pragma unroll
    for (int t = 0; t < 18; t++)
#pragma unroll
        for (int r = 0; r < 4; r++) S[t][r] = 0.f;

    const int a_row = ((lane >> 3) & 1) * 8 + (lane & 7);
    const int a_ch  = (lane >> 4) & 1;
    const int b_row = ((lane >> 4) & 1) * 8 + (lane & 7);
    const int b_ch  = (lane >> 3) & 1;

#pragma unroll
    for (int kc = 0; kc < 4; kc++) {
        unsigned qa[4];
        asm volatile("ldmatrix.sync.aligned.m8n8.x4.shared.b16 {%0,%1,%2,%3}, [%4];"
            : "=r"(qa[0]), "=r"(qa[1]), "=r"(qa[2]), "=r"(qa[3])
            : "r"(sQ + ASW(w * 16 + a_row, kc * 2 + a_ch)));
#pragma unroll
        for (int u = 0; u < 9; u++) {
            unsigned kb[4];
            asm volatile("ldmatrix.sync.aligned.m8n8.x4.shared.b16 {%0,%1,%2,%3}, [%4];"
                : "=r"(kb[0]), "=r"(kb[1]), "=r"(kb[2]), "=r"(kb[3])
                : "r"(sK + ASW(jb + u * 16 + b_row, kc * 2 + b_ch)));
            MMA_F16(S[2*u],   qa[0], qa[1], qa[2], qa[3], kb[0], kb[1]);
            MMA_F16(S[2*u+1], qa[0], qa[1], qa[2], qa[3], kb[2], kb[3]);
        }
    }

    // ---- masked softmax + sink gating on fragments ----
    const float snk = sinks[h];
    float wsc[2];
#pragma unroll
    for (int r01 = 0; r01 < 2; r01++) {
        const int i = iw + g + 8 * r01;
        float m = -1e30f;
#pragma unroll
        for (int t = 0; t < 18; t++) {
#pragma unroll
            for (int e = 0; e < 2; e++) {
                const int j = wlo + t * 8 + 2 * tg + e;
                const bool v = (j <= i) && (i - j < WINDOW);
                float s = v ? S[t][r01 * 2 + e] : -1e30f;
                S[t][r01 * 2 + e] = s;
                m = fmaxf(m, s);
            }
        }
        m = fmaxf(m, __shfl_xor_sync(0xffffffffu, m, 1));
        m = fmaxf(m, __shfl_xor_sync(0xffffffffu, m, 2));

        const float ml = m * L2E;
        float sum = 0.f;
#pragma unroll
        for (int t = 0; t < 18; t++) {
#pragma unroll
            for (int e = 0; e < 2; e++) {
                const float p = fexp(fmaf(S[t][r01 * 2 + e], L2E, -ml));
                S[t][r01 * 2 + e] = p;
                sum += p;
            }
        }
        sum += __shfl_xor_sync(0xffffffffu, sum, 1);
        sum += __shfl_xor_sync(0xffffffffu, sum, 2);

        const float lse = m + logf(sum);
        wsc[r01] = (1.f / (1.f + expf(snk - lse))) / sum;
    }

    // convert P to fp16 fragments (A-operand layout)
    unsigned ph[18][2];
#pragma unroll
    for (int t = 0; t < 18; t++) {
        __half2 p0 = __floats2half2_rn(S[t][0] * wsc[0], S[t][1] * wsc[0]);
        __half2 p1 = __floats2half2_rn(S[t][2] * wsc[1], S[t][3] * wsc[1]);
        ph[t][0] = *(unsigned*)&p0;
        ph[t][1] = *(unsigned*)&p1;
    }

    // ---- PV: out[16 x 64] ----
    float O[8][4];
#pragma unroll
    for (int t = 0; t < 8; t++)
#pragma unroll
        for (int r = 0; r < 4; r++) O[t][r] = 0.f;

    const int v_row = ((lane >> 3) & 1) * 8 + (lane & 7);
    const int v_ch  = (lane >> 4) & 1;

#pragma unroll
    for (int u = 0; u < 9; u++) {
        const unsigned pa0 = ph[2*u][0],   pa1 = ph[2*u][1];
        const unsigned pa2 = ph[2*u+1][0], pa3 = ph[2*u+1][1];
#pragma unroll
        for (int dg = 0; dg < 4; dg++) {
            unsigned vb[4];
            asm volatile("ldmatrix.sync.aligned.m8n8.x4.trans.shared.b16 {%0,%1,%2,%3}, [%4];"
                : "=r"(vb[0]), "=r"(vb[1]), "=r"(vb[2]), "=r"(vb[3])
                : "r"(sV + ASW(jb + u * 16 + v_row, dg * 2 + v_ch)));
            MMA_F16(O[2*dg],   pa0, pa1, pa2, pa3, vb[0], vb[1]);
            MMA_F16(O[2*dg+1], pa0, pa1, pa2, pa3, vb[2], vb[3]);
        }
    }

    // ---- write output (fp16) ----
#pragma unroll
    for (int t = 0; t < 8; t++) {
        const int col = h * HD + t * 8 + 2 * tg;
        __half2 o0 = __floats2half2_rn(O[t][0], O[t][1]);
        __half2 o1 = __floats2half2_rn(O[t][2], O[t][3]);
        *(__half2*)(o16 + (size_t)(iw + g) * QDIM + col)     = o0;
        *(__half2*)(o16 + (size_t)(iw + g + 8) * QDIM + col) = o1;
    }
}

// ---------------------------------------------------------------------------
extern "C" void kernel_launch(void* const* d_in, const int* in_sizes, int n_in,
                              void* d_out, int out_size)
{
    const float* x     = (const float*)d_in[0];
    const float* rope  = (const float*)d_in[1];
    const float* wq_w  = (const float*)d_in[2];
    const float* wq_b  = (const float*)d_in[3];
    const float* wk_w  = (const float*)d_in[4];
    const float* wk_b  = (const float*)d_in[5];
    const float* wv_w  = (const float*)d_in[6];
    const float* wv_b  = (const float*)d_in[7];
    const float* wo_w  = (const float*)d_in[8];
    const float* wo_b  = (const float*)d_in[9];
    const float* sinks = (const float*)d_in[10];
    float* out = (float*)d_out;

    float *qkv, *bqkv;
    cudaGetSymbolAddress((void**)&qkv,  g_qkv);
    cudaGetSymbolAddress((void**)&bqkv, g_bqkv);

    f16 *x16, *wc, *wo, *a16;
    cudaGetSymbolAddress((void**)&x16, g_x16);
    cudaGetSymbolAddress((void**)&wc, g_wc); cudaGetSymbolAddress((void**)&wo, g_wo);
    cudaGetSymbolAddress((void**)&a16, g_a16);

    cudaFuncSetAttribute(gemm_f16, cudaFuncAttributeMaxDynamicSharedMemorySize,
                         GSMEM_BYTES);
    cudaFuncSetAttribute(attn_kernel, cudaFuncAttributeMaxDynamicSharedMemorySize,
                         ASMEM_BYTES);

    // fused prep
    prep<<<(unsigned)((PREP_THREADS + 255) / 256), 256>>>(
        x, wq_w, wk_w, wv_w, wo_w, wq_b, wk_b, wv_b,
        x16, wc, wo, bqkv);

    // fused QKV projection: [2048 x 5120], 640 CTAs
    gemm_f16<<<dim3(QKVN / 128, SEQ / 128), 256, GSMEM_BYTES>>>(
        x16, wc, bqkv, qkv, SEQ, QKVN, DIM);

    // fused RoPE (q + k)
    rope_all<<<(SEQ * (NH + NKV) * 32 + 255) / 256, 256>>>(qkv, rope);

    // flash-style tensor-core attention: 64 heads x 16 q-blocks = 1024 CTAs
    attn_kernel<<<NH * (SEQ / 128), 256, ASMEM_BYTES>>>(qkv, sinks, a16);

    // O-projection
    gemm_f16<<<dim3((DIM + 127) / 128, SEQ / 128), 256, GSMEM_BYTES>>>(
        a16, wo, wo_b, out, SEQ, DIM, QDIM);
}

// round 17
// speedup vs baseline: 1.6504x; 1.0602x over previous
#include <cuda_runtime.h>
#include <cuda_fp16.h>
#include <math.h>

#define SEQ 2048
#define DIM 2880
#define NH 64
#define NKV 8
#define HD 64
#define QDIM (NH*HD)     // 4096
#define KVDIM (NKV*HD)   // 512
#define QKVN 5120        // 4096 + 512 + 512
#define KOFF 4096
#define VOFF 4608
#define WINDOW 128

typedef __half f16;

// scratch
__device__ float g_bqkv[QKVN];
__device__ f16 g_x16[SEQ * DIM];       // x (fp16)
__device__ f16 g_wc[QKVN * DIM];       // concat wq|wk|wv (fp16; wq pre-scaled)
__device__ f16 g_wo[DIM * QDIM];       // wo (fp16)
__device__ f16 g_qkv16[SEQ * QKVN];    // roped q|k|v (fp16)
__device__ f16 g_a16[SEQ * QDIM];      // attn out (fp16)

// ---------------------------------------------------------------------------
// Fused prep: x -> fp16, wq*scale/wk/wv -> wc fp16, wo -> fp16, bias concat
// (q bias pre-scaled).
// ---------------------------------------------------------------------------
#define R0 (SEQ*DIM/8)
#define R1 (QDIM*DIM/8)
#define R2 (KVDIM*DIM/8)
#define R3 (KVDIM*DIM/8)
#define R4 ((size_t)DIM*QDIM/8)
#define R5 (QKVN/8)
#define PREP_THREADS (R0+R1+R2+R3+R4+R5)
#define QSCALE 0.16832169945461f       // (0.1*ln(32)+1)/8

__device__ __forceinline__ void conv8s(const float* __restrict__ s,
                                       f16* __restrict__ d, float mul) {
    float4 a = *(const float4*)s;
    float4 b = *(const float4*)(s + 4);
    __half2 hh[4];
    hh[0] = __halves2half2(__float2half_rn(a.x * mul), __float2half_rn(a.y * mul));
    hh[1] = __halves2half2(__float2half_rn(a.z * mul), __float2half_rn(a.w * mul));
    hh[2] = __halves2half2(__float2half_rn(b.x * mul), __float2half_rn(b.y * mul));
    hh[3] = __halves2half2(__float2half_rn(b.z * mul), __float2half_rn(b.w * mul));
    *(uint4*)d = *(uint4*)hh;
}

__global__ void prep(const float* __restrict__ x,
                     const float* __restrict__ wq, const float* __restrict__ wk,
                     const float* __restrict__ wv, const float* __restrict__ wo,
                     const float* __restrict__ qb, const float* __restrict__ kb,
                     const float* __restrict__ vb,
                     f16* __restrict__ x16,
                     f16* __restrict__ wc, f16* __restrict__ wo16,
                     float* __restrict__ bqkv)
{
    long t = (long)blockIdx.x * blockDim.x + threadIdx.x;
    if (t < (long)R0) { conv8s(x + t * 8, x16 + t * 8, 1.f); return; }
    t -= R0;
    if (t < (long)R1) { conv8s(wq + t * 8, wc + t * 8, QSCALE); return; }
    t -= R1;
    if (t < (long)R2) { conv8s(wk + t * 8, wc + (size_t)KOFF * DIM + t * 8, 1.f); return; }
    t -= R2;
    if (t < (long)R3) { conv8s(wv + t * 8, wc + (size_t)VOFF * DIM + t * 8, 1.f); return; }
    t -= R3;
    if (t < (long)R4) { conv8s(wo + t * 8, wo16 + t * 8, 1.f); return; }
    t -= R4;
    if (t < (long)R5) {
        const int i = (int)t * 8;
#pragma unroll
        for (int j = 0; j < 8; j++) {
            const int c = i + j;
            bqkv[c] = (c < KOFF) ? qb[c] * QSCALE
                                 : (c < VOFF ? kb[c - KOFF] : vb[c - VOFF]);
        }
    }
}

// ---------------------------------------------------------------------------
// common GEMM pieces
// ---------------------------------------------------------------------------
#define TILEB 16384u
#define STAGEB (2u*TILEB)
#define NSTG 3
#define GSMEM_BYTES (NSTG*STAGEB)   // 96 KB

__device__ __forceinline__ void cpa16(unsigned dst, const void* src) {
    asm volatile("cp.async.cg.shared.global [%0], [%1], 16;" :: "r"(dst), "l"(src));
}
__device__ __forceinline__ void cpa16p(unsigned dst, const void* src, int sz) {
    asm volatile("cp.async.cg.shared.global [%0], [%1], 16, %2;"
                 :: "r"(dst), "l"(src), "r"(sz));
}

#define MMA_F16(d, a0, a1, a2, a3, b0, b1)                                     \
    asm volatile("mma.sync.aligned.m16n8k16.row.col.f32.f16.f16.f32 "          \
                 "{%0,%1,%2,%3}, {%4,%5,%6,%7}, {%8,%9}, {%0,%1,%2,%3};"       \
                 : "+f"((d)[0]), "+f"((d)[1]), "+f"((d)[2]), "+f"((d)[3])      \
                 : "r"(a0), "r"(a1), "r"(a2), "r"(a3), "r"(b0), "r"(b1))

#define SWOFF(r, c) ((unsigned)((r) * 128 + ((((c) ^ ((r) & 7))) << 4)))

#define GEMM_MAINLOOP(ACC_M)                                                   \
    float acc[ACC_M][8][4];                                                    \
    _Pragma("unroll")                                                          \
    for (int mi = 0; mi < ACC_M; mi++)                                         \
        _Pragma("unroll")                                                      \
        for (int ni = 0; ni < 8; ni++)                                         \
            _Pragma("unroll")                                                  \
            for (int r = 0; r < 4; r++) acc[mi][ni][r] = 0.f;                  \
    ISSUE_STAGE(0, 0);                                                         \
    ISSUE_STAGE(1, 64);                                                        \
    const int a_row = ((lane >> 3) & 1) * 8 + (lane & 7);                      \
    const int a_ch  = (lane >> 4) & 1;                                         \
    const int b_row = ((lane >> 4) & 1) * 8 + (lane & 7);                      \
    const int b_ch  = (lane >> 3) & 1;                                         \
    for (int kt = 0; kt < KT; kt++) {                                          \
        asm volatile("cp.async.wait_group %0;" :: "n"(1));                     \
        __syncthreads();                                                       \
        if (kt + 2 < KT) ISSUE_STAGE((kt + 2) % NSTG, (kt + 2) * 64);          \
        else             asm volatile("cp.async.commit_group;");               \
        const unsigned stb = sb + (unsigned)(kt % NSTG) * STAGEB;              \
        _Pragma("unroll")                                                      \
        for (int ks = 0; ks < 4; ks++) {                                       \
            unsigned fA[ACC_M][4], fB[8][2];                                   \
            const int ca = ks * 2 + a_ch;                                      \
            const int cb = ks * 2 + b_ch;                                      \
            _Pragma("unroll")                                                  \
            for (int mi = 0; mi < ACC_M; mi++) {                               \
                const int r = wm + mi * 16 + a_row;                            \
                asm volatile("ldmatrix.sync.aligned.m8n8.x4.shared.b16 "       \
                    "{%0,%1,%2,%3}, [%4];"                                     \
                    : "=r"(fA[mi][0]), "=r"(fA[mi][1]),                        \
                      "=r"(fA[mi][2]), "=r"(fA[mi][3])                         \
                    : "r"(stb + SWOFF(r, ca)));                                \
            }                                                                  \
            _Pragma("unroll")                                                  \
            for (int p = 0; p < 4; p++) {                                      \
                const int r = wn + p * 16 + b_row;                             \
                asm volatile("ldmatrix.sync.aligned.m8n8.x4.shared.b16 "       \
                    "{%0,%1,%2,%3}, [%4];"                                     \
                    : "=r"(fB[2*p][0]), "=r"(fB[2*p][1]),                      \
                      "=r"(fB[2*p+1][0]), "=r"(fB[2*p+1][1])                   \
                    : "r"(stb + TILEB + SWOFF(r, cb)));                        \
            }                                                                  \
            _Pragma("unroll")                                                  \
            for (int ni = 0; ni < 8; ni++)                                     \
                _Pragma("unroll")                                              \
                for (int mi = 0; mi < ACC_M; mi++)                             \
                    MMA_F16(acc[mi][ni], fA[mi][0], fA[mi][1], fA[mi][2],      \
                            fA[mi][3], fB[ni][0], fB[ni][1]);                  \
        }                                                                      \
    }

// ---------------------------------------------------------------------------
// QKV GEMM with fused RoPE epilogue -> fp16 qkv buffer.
// Block 128x128, BK=64, 3-stage ring, 8 warps (4m x 2n), 2 CTAs/SM.
// N = 5120 (no column guard needed). Rope applied to cols < VOFF.
// ---------------------------------------------------------------------------
__global__ __launch_bounds__(256, 2) void gemm_qkv(
    const f16* __restrict__ A, const f16* __restrict__ B,
    const float* __restrict__ bias, const float* __restrict__ rope,
    f16* __restrict__ C16, int M, int N, int K)
{
    extern __shared__ char dsm[];
    unsigned sb;
    { unsigned long long t = __cvta_generic_to_shared(dsm); sb = (unsigned)t; }

    const int tid  = threadIdx.x;
    const int wid  = tid >> 5;
    const int lane = tid & 31;
    const int bm   = blockIdx.y * 128;
    const int bn   = blockIdx.x * 128;
    const int wm   = (wid & 3) * 32;
    const int wn   = (wid >> 2) * 64;
    const int g    = lane >> 2;
    const int tg   = lane & 3;

    const int KT = K / 64;
    const int r0c = tid >> 3;
    const int c0c = tid & 7;

#define ISSUE_STAGE(sidx, k0)                                                  \
    do {                                                                       \
        const unsigned tb = sb + (unsigned)(sidx) * STAGEB;                    \
        _Pragma("unroll")                                                      \
        for (int it = 0; it < 4; it++) {                                       \
            const int r = r0c + it * 32;                                       \
            const unsigned so = SWOFF(r, c0c);                                 \
            cpa16(tb + so,         A + (size_t)(bm + r) * K + (k0) + c0c * 8); \
            cpa16(tb + TILEB + so, B + (size_t)(bn + r) * K + (k0) + c0c * 8); \
        }                                                                      \
        asm volatile("cp.async.commit_group;");                                \
    } while (0)

    GEMM_MAINLOOP(2)
#undef ISSUE_STAGE

    // epilogue: bias + rope (cols < VOFF) + fp16 store
    const bool dorope = (bn + wn) < VOFF;   // warp-uniform (64-col head tiles)
#pragma unroll
    for (int mi = 0; mi < 2; mi++) {
        const int row0 = bm + wm + mi * 16 + g;
#pragma unroll
        for (int ni = 0; ni < 4; ni++) {
            const int col = bn + wn + ni * 8 + tg * 2;   // lo col
            const int d   = col & 63;                    // 0..31
            const float blo0 = bias[col],      blo1 = bias[col + 1];
            const float bhi0 = bias[col + 32], bhi1 = bias[col + 33];
#pragma unroll
            for (int r01 = 0; r01 < 2; r01++) {
                const int r = row0 + r01 * 8;
                const float xlo0 = acc[mi][ni][2 * r01 + 0] + blo0;
                const float xlo1 = acc[mi][ni][2 * r01 + 1] + blo1;
                const float xhi0 = acc[mi][ni + 4][2 * r01 + 0] + bhi0;
                const float xhi1 = acc[mi][ni + 4][2 * r01 + 1] + bhi1;
                float olo0 = xlo0, olo1 = xlo1, ohi0 = xhi0, ohi1 = xhi1;
                if (dorope) {
                    const float* rp = rope + (size_t)r * 128;
                    const float2 cl = *(const float2*)(rp + d);
                    const float2 ch = *(const float2*)(rp + d + 32);
                    const float2 sl = *(const float2*)(rp + 64 + d);
                    const float2 sh = *(const float2*)(rp + 96 + d);
                    olo0 = xlo0 * cl.x - xhi0 * sl.x;
                    olo1 = xlo1 * cl.y - xhi1 * sl.y;
                    ohi0 = xhi0 * ch.x + xlo0 * sh.x;
                    ohi1 = xhi1 * ch.y + xlo1 * sh.y;
                }
                *(__half2*)(C16 + (size_t)r * QKVN + col) =
                    __floats2half2_rn(olo0, olo1);
                *(__half2*)(C16 + (size_t)r * QKVN + col + 32) =
                    __floats2half2_rn(ohi0, ohi1);
            }
        }
    }
}

// ---------------------------------------------------------------------------
// O-proj GEMM (NT): C = A*B^T + bias, fp32 out.  [R11-proven config]
// ---------------------------------------------------------------------------
__global__ __launch_bounds__(256, 2) void gemm_f16(
    const f16* __restrict__ A, const f16* __restrict__ B,
    const float* __restrict__ bias, float* __restrict__ C,
    int M, int N, int K)
{
    extern __shared__ char dsm[];
    unsigned sb;
    { unsigned long long t = __cvta_generic_to_shared(dsm); sb = (unsigned)t; }

    const int tid  = threadIdx.x;
    const int wid  = tid >> 5;
    const int lane = tid & 31;
    const int bm   = blockIdx.y * 128;
    const int bn   = blockIdx.x * 128;
    const int wm   = (wid & 3) * 32;
    const int wn   = (wid >> 2) * 64;
    const int g    = lane >> 2;
    const int tg   = lane & 3;

    const int KT = K / 64;
    const int r0c = tid >> 3;
    const int c0c = tid & 7;

#define ISSUE_STAGE(sidx, k0)                                                  \
    do {                                                                       \
        const unsigned tb = sb + (unsigned)(sidx) * STAGEB;                    \
        _Pragma("unroll")                                                      \
        for (int it = 0; it < 4; it++) {                                       \
            const int r = r0c + it * 32;                                       \
            const unsigned so = SWOFF(r, c0c);                                 \
            const size_t ao = (size_t)(bm + r) * K + (k0) + c0c * 8;           \
            const int brw = bn + r;                                            \
            const int pz  = (brw < N) ? 16 : 0;                                \
            const size_t bo = (size_t)((brw < N) ? brw : 0) * K + (k0) + c0c * 8; \
            cpa16 (tb + so,         A + ao);                                   \
            cpa16p(tb + TILEB + so, B + bo, pz);                               \
        }                                                                      \
        asm volatile("cp.async.commit_group;");                                \
    } while (0)

    GEMM_MAINLOOP(2)
#undef ISSUE_STAGE

#pragma unroll
    for (int mi = 0; mi < 2; mi++) {
        const int row = bm + wm + mi * 16 + g;
#pragma unroll
        for (int ni = 0; ni < 8; ni++) {
            const int col = bn + wn + ni * 8 + tg * 2;
            if (col < N) {
                const float bx = bias[col], by = bias[col + 1];
                float2 v0 = make_float2(acc[mi][ni][0] + bx, acc[mi][ni][1] + by);
                float2 v1 = make_float2(acc[mi][ni][2] + bx, acc[mi][ni][3] + by);
                *(float2*)(C + (size_t)row * N + col)       = v0;
                *(float2*)(C + (size_t)(row + 8) * N + col) = v1;
            }
        }
    }
}

// ---------------------------------------------------------------------------
// FMA-pipe exp: input y = x*log2(e), x <= 0 (or masked very negative).
// ---------------------------------------------------------------------------
__device__ __forceinline__ float fexp(float y)
{
    y = fmaxf(y, -126.f);
    const float r  = y + 12582912.f;
    const float nf = r - 12582912.f;
    const float f  = y - nf;
    float p = 1.3276472e-3f;
    p = fmaf(p, f, 9.6180289e-3f);
    p = fmaf(p, f, 5.5504109e-2f);
    p = fmaf(p, f, 2.4022651e-1f);
    p = fmaf(p, f, 6.9314718e-1f);
    p = fmaf(p, f, 1.0f);
    const int ni = __float_as_int(r) - 0x4B400000;
    const float sc = __int_as_float((ni + 127) << 23);
    return p * sc;
}

// ---------------------------------------------------------------------------
// Flash-style tensor-core attention + sink gating (fp16 qkv input, cp.async
// staging, Q pre-scaled). CTA = (head, 128 queries), warp = 16 queries.
// ---------------------------------------------------------------------------
#define JC 256
#define ASMEM_BYTES (JC*128 + JC*128 + 128*128)   // 80 KB

#define ASW(r, c) ((unsigned)((r) * 128 + ((((c) ^ ((r) & 7))) << 4)))

__global__ __launch_bounds__(256, 2) void attn_kernel(
    const f16* __restrict__ qkv16, const float* __restrict__ sinks,
    f16* __restrict__ o16)
{
    extern __shared__ char asmc_[];
    unsigned sbase;
    { unsigned long long t = __cvta_generic_to_shared(asmc_); sbase = (unsigned)t; }
    const unsigned sK = sbase;
    const unsigned sV = sbase + JC * 128;
    const unsigned sQ = sbase + 2 * JC * 128;

    const float L2E = 1.44269504089f;
    const int tid  = threadIdx.x;
    const int w    = tid >> 5;
    const int lane = tid & 31;
    const int g    = lane >> 2;
    const int tg   = lane & 3;
    const int h    = blockIdx.x >> 4;
    const int ib   = blockIdx.x & 15;
    const int i0   = ib * 128;
    const int kvh  = h >> 3;

    int jmin = i0 - (WINDOW - 1); if (jmin < 0) jmin = 0;
    const int jcnt = i0 + 127 - jmin + 1;    // <= 255

    // stage K, V via cp.async (zero-fill rows >= jcnt)
#pragma unroll
    for (int it = 0; it < 8; it++) {
        const int idx = tid + it * 256;
        const int row = idx >> 3, c = idx & 7;
        const int pz = (row < jcnt) ? 16 : 0;
        int gr = jmin + row; if (gr > SEQ - 1) gr = SEQ - 1;
        const f16* src = qkv16 + (size_t)gr * QKVN + kvh * HD + c * 8;
        cpa16p(sK + ASW(row, c), src + KOFF, pz);
        cpa16p(sV + ASW(row, c), src + VOFF, pz);
    }
    // stage Q (pre-scaled, roped)
#pragma unroll
    for (int it = 0; it < 4; it++) {
        const int idx = tid + it * 256;
        const int row = idx >> 3, c = idx & 7;
        cpa16(sQ + ASW(row, c),
              qkv16 + (size_t)(i0 + row) * QKVN + h * HD + c * 8);
    }
    asm volatile("cp.async.commit_group;");
    asm volatile("cp.async.wait_group 0;");
    __syncthreads();

    const int iw  = i0 + w * 16;
    int wlo = iw - (WINDOW - 1); if (wlo < 0) wlo = 0;
    const int jb  = wlo - jmin;              // multiple of 16

    // QK^T
    float S[18][4];
#pragma unroll
    for (int t = 0; t < 18; t++)
#pragma unroll
        for (int r = 0; r < 4; r++) S[t][r] = 0.f;

    const int a_row = ((lane >> 3) & 1) * 8 + (lane & 7);
    const int a_ch  = (lane >> 4) & 1;
    const int b_row = ((lane >> 4) & 1) * 8 + (lane & 7);
    const int b_ch  = (lane >> 3) & 1;

#pragma unroll
    for (int kc = 0; kc < 4; kc++) {
        unsigned qa[4];
        asm volatile("ldmatrix.sync.aligned.m8n8.x4.shared.b16 {%0,%1,%2,%3}, [%4];"
            : "=r"(qa[0]), "=r"(qa[1]), "=r"(qa[2]), "=r"(qa[3])
            : "r"(sQ + ASW(w * 16 + a_row, kc * 2 + a_ch)));
#pragma unroll
        for (int u = 0; u < 9; u++) {
            unsigned kb[4];
            asm volatile("ldmatrix.sync.aligned.m8n8.x4.shared.b16 {%0,%1,%2,%3}, [%4];"
                : "=r"(kb[0]), "=r"(kb[1]), "=r"(kb[2]), "=r"(kb[3])
                : "r"(sK + ASW(jb + u * 16 + b_row, kc * 2 + b_ch)));
            MMA_F16(S[2*u],   qa[0], qa[1], qa[2], qa[3], kb[0], kb[1]);
            MMA_F16(S[2*u+1], qa[0], qa[1], qa[2], qa[3], kb[2], kb[3]);
        }
    }

    // masked softmax + sink gating
    const float snk = sinks[h];
    float wsc[2];
#pragma unroll
    for (int r01 = 0; r01 < 2; r01++) {
        const int i = iw + g + 8 * r01;
        float m = -1e30f;
#pragma unroll
        for (int t = 0; t < 18; t++) {
#pragma unroll
            for (int e = 0; e < 2; e++) {
                const int j = wlo + t * 8 + 2 * tg + e;
                const bool v = (j <= i) && (i - j < WINDOW);
                float s = v ? S[t][r01 * 2 + e] : -1e30f;
                S[t][r01 * 2 + e] = s;
                m = fmaxf(m, s);
            }
        }
        m = fmaxf(m, __shfl_xor_sync(0xffffffffu, m, 1));
        m = fmaxf(m, __shfl_xor_sync(0xffffffffu, m, 2));

        const float ml = m * L2E;
        float sum = 0.f;
#pragma unroll
        for (int t = 0; t < 18; t++) {
#pragma unroll
            for (int e = 0; e < 2; e++) {
                const float p = fexp(fmaf(S[t][r01 * 2 + e], L2E, -ml));
                S[t][r01 * 2 + e] = p;
                sum += p;
            }
        }
        sum += __shfl_xor_sync(0xffffffffu, sum, 1);
        sum += __shfl_xor_sync(0xffffffffu, sum, 2);

        const float lse = m + logf(sum);
        wsc[r01] = (1.f / (1.f + expf(snk - lse))) / sum;
    }

    unsigned ph[18][2];
#pragma unroll
    for (int t = 0; t < 18; t++) {
        __half2 p0 = __floats2half2_rn(S[t][0] * wsc[0], S[t][1] * wsc[0]);
        __half2 p1 = __floats2half2_rn(S[t][2] * wsc[1], S[t][3] * wsc[1]);
        ph[t][0] = *(unsigned*)&p0;
        ph[t][1] = *(unsigned*)&p1;
    }

    // PV
    float O[8][4];
#pragma unroll
    for (int t = 0; t < 8; t++)
#pragma unroll
        for (int r = 0; r < 4; r++) O[t][r] = 0.f;

    const int v_row = ((lane >> 3) & 1) * 8 + (lane & 7);
    const int v_ch  = (lane >> 4) & 1;

#pragma unroll
    for (int u = 0; u < 9; u++) {
        const unsigned pa0 = ph[2*u][0],   pa1 = ph[2*u][1];
        const unsigned pa2 = ph[2*u+1][0], pa3 = ph[2*u+1][1];
#pragma unroll
        for (int dg = 0; dg < 4; dg++) {
            unsigned vb[4];
            asm volatile("ldmatrix.sync.aligned.m8n8.x4.trans.shared.b16 {%0,%1,%2,%3}, [%4];"
                : "=r"(vb[0]), "=r"(vb[1]), "=r"(vb[2]), "=r"(vb[3])
                : "r"(sV + ASW(jb + u * 16 + v_row, dg * 2 + v_ch)));
            MMA_F16(O[2*dg],   pa0, pa1, pa2, pa3, vb[0], vb[1]);
            MMA_F16(O[2*dg+1], pa0, pa1, pa2, pa3, vb[2], vb[3]);
        }
    }

#pragma unroll
    for (int t = 0; t < 8; t++) {
        const int col = h * HD + t * 8 + 2 * tg;
        __half2 o0 = __floats2half2_rn(O[t][0], O[t][1]);
        __half2 o1 = __floats2half2_rn(O[t][2], O[t][3]);
        *(__half2*)(o16 + (size_t)(iw + g) * QDIM + col)     = o0;
        *(__half2*)(o16 + (size_t)(iw + g + 8) * QDIM + col) = o1;
    }
}

// ---------------------------------------------------------------------------
extern "C" void kernel_launch(void* const* d_in, const int* in_sizes, int n_in,
                              void* d_out, int out_size)
{
    const float* x     = (const float*)d_in[0];
    const float* rope  = (const float*)d_in[1];
    const float* wq_w  = (const float*)d_in[2];
    const float* wq_b  = (const float*)d_in[3];
    const float* wk_w  = (const float*)d_in[4];
    const float* wk_b  = (const float*)d_in[5];
    const float* wv_w  = (const float*)d_in[6];
    const float* wv_b  = (const float*)d_in[7];
    const float* wo_w  = (const float*)d_in[8];
    const float* wo_b  = (const float*)d_in[9];
    const float* sinks = (const float*)d_in[10];
    float* out = (float*)d_out;

    float* bqkv;
    cudaGetSymbolAddress((void**)&bqkv, g_bqkv);

    f16 *x16, *wc, *wo, *qkv16, *a16;
    cudaGetSymbolAddress((void**)&x16, g_x16);
    cudaGetSymbolAddress((void**)&wc, g_wc);
    cudaGetSymbolAddress((void**)&wo, g_wo);
    cudaGetSymbolAddress((void**)&qkv16, g_qkv16);
    cudaGetSymbolAddress((void**)&a16, g_a16);

    cudaFuncSetAttribute(gemm_qkv, cudaFuncAttributeMaxDynamicSharedMemorySize,
                         GSMEM_BYTES);
    cudaFuncSetAttribute(gemm_f16, cudaFuncAttributeMaxDynamicSharedMemorySize,
                         GSMEM_BYTES);
    cudaFuncSetAttribute(attn_kernel, cudaFuncAttributeMaxDynamicSharedMemorySize,
                         ASMEM_BYTES);

    // fused prep (wq and q-bias pre-scaled)
    prep<<<(unsigned)((PREP_THREADS + 255) / 256), 256>>>(
        x, wq_w, wk_w, wv_w, wo_w, wq_b, wk_b, wv_b,
        x16, wc, wo, bqkv);

    // fused QKV projection + RoPE epilogue -> fp16 qkv
    gemm_qkv<<<dim3(QKVN / 128, SEQ / 128), 256, GSMEM_BYTES>>>(
        x16, wc, bqkv, rope, qkv16, SEQ, QKVN, DIM);

    // flash-style tensor-core attention
    attn_kernel<<<NH * (SEQ / 128), 256, ASMEM_BYTES>>>(qkv16, sinks, a16);

    // O-projection (fp32 out)
    gemm_f16<<<dim3((DIM + 127) / 128, SEQ / 128), 256, GSMEM_BYTES>>>(
        a16, wo, wo_b, out, SEQ, DIM, QDIM);
}